// round 2
// baseline (speedup 1.0000x reference)
#include <cuda_runtime.h>
#include <math.h>

// Problem constants
#define BB 2
#define SS 2048
#define DD 1024
#define HH 16
#define DHD 64
#define MM (BB*SS)   // 4096

// Scratch (allocations are forbidden; __device__ globals are the sanctioned path)
__device__ float g_q[(size_t)BB*HH*SS*DHD];   // [B,H,S,DH] 16MB
__device__ float g_k[(size_t)BB*HH*SS*DHD];
__device__ float g_v[(size_t)BB*HH*SS*DHD];
__device__ float g_att[(size_t)BB*SS*DD];     // [B,S,D] 16MB

// ---------------------------------------------------------------------------
// Kernel 1: fused QKV projection.
// q[b,h,s,e] = sum_d x[b,s,d] * Wq[h,d,e] + bq[h,e]   (same for k, v)
// 48 column-tiles of a 4096x(3*1024) GEMM. BM=BN=64, BK=16.
// Micro-tile: 4 CONSECUTIVE rows x 4 CONSECUTIVE cols -> LDS.128 operand fetch.
// grid: (M/64, 3*H), block: 256
// ---------------------------------------------------------------------------
__global__ __launch_bounds__(256) void qkv_kernel(
    const float* __restrict__ x,
    const float* __restrict__ Wq, const float* __restrict__ Wk, const float* __restrict__ Wv,
    const float* __restrict__ bq, const float* __restrict__ bk, const float* __restrict__ bv)
{
    __shared__ float As[16][68];   // A transposed [k][m], stride 68 (16B-aligned pad)
    __shared__ float Bs[16][64];   // W tile [k][n]

    const int tid = threadIdx.x;
    const int ty = tid >> 4;       // 0..15 -> rows ty*4..ty*4+3
    const int tx = tid & 15;       // 0..15 -> cols tx*4..tx*4+3
    const int m0 = blockIdx.x * 64;
    const int which = blockIdx.y / HH;   // 0=q 1=k 2=v
    const int h = blockIdx.y % HH;

    const float* W    = (which == 0) ? Wq : (which == 1) ? Wk : Wv;
    const float* bias = (which == 0) ? bq : (which == 1) ? bk : bv;
    float*       outp = (which == 0) ? g_q : (which == 1) ? g_k : g_v;
    W    += (size_t)h * DD * DHD;
    bias += h * DHD;

    const int arow = tid >> 2, ac4 = tid & 3;    // A loader: 64 rows x 4 float4
    const int brow = tid >> 4, bc4 = tid & 15;   // B loader: 16 rows x 16 float4

    float acc[4][4] = {};

    for (int k0 = 0; k0 < DD; k0 += 16) {
        float4 av = *(const float4*)&x[(size_t)(m0 + arow) * DD + k0 + ac4 * 4];
        As[ac4*4+0][arow] = av.x;
        As[ac4*4+1][arow] = av.y;
        As[ac4*4+2][arow] = av.z;
        As[ac4*4+3][arow] = av.w;
        *(float4*)&Bs[brow][bc4*4] = *(const float4*)&W[(size_t)(k0 + brow) * DHD + bc4 * 4];
        __syncthreads();
        #pragma unroll
        for (int kk = 0; kk < 16; kk++) {
            const float4 a4 = *(const float4*)&As[kk][ty*4];
            const float4 b4 = *(const float4*)&Bs[kk][tx*4];
            const float a[4] = {a4.x, a4.y, a4.z, a4.w};
            const float b[4] = {b4.x, b4.y, b4.z, b4.w};
            #pragma unroll
            for (int i = 0; i < 4; i++)
                #pragma unroll
                for (int j = 0; j < 4; j++)
                    acc[i][j] += a[i] * b[j];
        }
        __syncthreads();
    }

    const float4 bi = *(const float4*)&bias[tx*4];
    const float bv4[4] = {bi.x, bi.y, bi.z, bi.w};
    #pragma unroll
    for (int i = 0; i < 4; i++) {
        const int m = m0 + ty*4 + i;
        const int b_ = m >> 11;           // m / S
        const int s  = m & (SS - 1);      // m % S
        float4 o4 = make_float4(acc[i][0] + bv4[0], acc[i][1] + bv4[1],
                                acc[i][2] + bv4[2], acc[i][3] + bv4[3]);
        *(float4*)&outp[(((size_t)b_ * HH + h) * SS + s) * DHD + tx*4] = o4;
    }
}

// ---------------------------------------------------------------------------
// Kernel 2: flash-style attention per (b,h). Q-tile 64 rows, KV-tiles of 64.
// Row ownership (ty*4+i) is identical in the QK^T and PV phases (softmax state
// is thread-local). Key mapping differs per phase: scattered (tx+16j) for QK^T
// (2-way K-read conflicts), consecutive (tx*4+j) for PV (LDS.128 on V).
// grid: (S/64, H, B), block: 256, dynamic smem 50176 B
// ---------------------------------------------------------------------------
#define ATTN_SMEM_BYTES ((64*64 + 64*68 + 64*64) * 4)

__global__ __launch_bounds__(256) void attn_kernel()
{
    extern __shared__ float smem[];
    float (*Qs)[64] = reinterpret_cast<float(*)[64]>(smem);                 // [row][d]
    float (*Ks)[68] = reinterpret_cast<float(*)[68]>(smem + 64*64);         // [key][d]
    float (*Vs)[64] = reinterpret_cast<float(*)[64]>(smem + 64*64 + 64*68); // [key][d]
    float (*Ps)[68] = Ks;                                                   // alias: probs [row][key]

    const int tid = threadIdx.x;
    const int ty = tid >> 4;   // rows ty*4..ty*4+3
    const int tx = tid & 15;
    const int qt = blockIdx.x;
    const int h  = blockIdx.y;
    const int b  = blockIdx.z;

    const size_t head_base = ((size_t)b * HH + h) * SS;
    const int m0 = qt * 64;

    // Load Q tile (64 x 64)
    for (int t = tid; t < 64*16; t += 256) {
        const int r = t >> 4, c4 = t & 15;
        *(float4*)&Qs[r][c4*4] = *(const float4*)&g_q[(head_base + m0 + r) * DHD + c4*4];
    }

    float o[4][4] = {};
    float mrow[4] = {-1e30f, -1e30f, -1e30f, -1e30f};
    float lrow[4] = {};
    const float scale = 0.125f;  // 1/sqrt(64)

    __syncthreads();

    for (int kt = 0; kt < SS; kt += 64) {
        // Load K, V tiles
        for (int t = tid; t < 64*16; t += 256) {
            const int r = t >> 4, c4 = t & 15;
            *(float4*)&Ks[r][c4*4] = *(const float4*)&g_k[(head_base + kt + r) * DHD + c4*4];
            *(float4*)&Vs[r][c4*4] = *(const float4*)&g_v[(head_base + kt + r) * DHD + c4*4];
        }
        __syncthreads();

        // S = Q @ K^T : rows ty*4+i, keys tx+16j
        float sc[4][4] = {};
        #pragma unroll 8
        for (int d = 0; d < 64; d++) {
            float q[4], k[4];
            #pragma unroll
            for (int i = 0; i < 4; i++) q[i] = Qs[ty*4 + i][d];
            #pragma unroll
            for (int j = 0; j < 4; j++) k[j] = Ks[tx + 16*j][d];
            #pragma unroll
            for (int i = 0; i < 4; i++)
                #pragma unroll
                for (int j = 0; j < 4; j++)
                    sc[i][j] += q[i] * k[j];
        }

        // online softmax per row. The 16 lanes {(ty&1)*16 + tx} of each warp
        // jointly own a row's 64 keys; xor 1/2/4/8 reduces within that group.
        #pragma unroll
        for (int i = 0; i < 4; i++) {
            float mt = -1e30f;
            #pragma unroll
            for (int j = 0; j < 4; j++) { sc[i][j] *= scale; mt = fmaxf(mt, sc[i][j]); }
            #pragma unroll
            for (int off = 8; off >= 1; off >>= 1)
                mt = fmaxf(mt, __shfl_xor_sync(0xffffffffu, mt, off));
            const float mnew = fmaxf(mrow[i], mt);
            const float corr = __expf(mrow[i] - mnew);
            float ls = 0.f;
            #pragma unroll
            for (int j = 0; j < 4; j++) {
                const float p = __expf(sc[i][j] - mnew);
                sc[i][j] = p;
                ls += p;
            }
            #pragma unroll
            for (int off = 8; off >= 1; off >>= 1)
                ls += __shfl_xor_sync(0xffffffffu, ls, off);
            lrow[i] = lrow[i] * corr + ls;
            mrow[i] = mnew;
            #pragma unroll
            for (int j = 0; j < 4; j++) o[i][j] *= corr;
        }

        __syncthreads();   // everyone done reading Ks before P overwrites it
        #pragma unroll
        for (int i = 0; i < 4; i++)
            #pragma unroll
            for (int j = 0; j < 4; j++)
                Ps[ty*4 + i][tx + 16*j] = sc[i][j];   // stride-68 store: conflict-free
        __syncthreads();

        // O += P @ V : rows ty*4+i, dh cols tx*4+j (float4 V fetch)
        #pragma unroll 8
        for (int kk = 0; kk < 64; kk++) {
            float p[4];
            #pragma unroll
            for (int i = 0; i < 4; i++) p[i] = Ps[ty*4 + i][kk];
            const float4 v4 = *(const float4*)&Vs[kk][tx*4];
            const float v[4] = {v4.x, v4.y, v4.z, v4.w};
            #pragma unroll
            for (int i = 0; i < 4; i++)
                #pragma unroll
                for (int j = 0; j < 4; j++)
                    o[i][j] += p[i] * v[j];
        }
        __syncthreads();   // before next tile overwrites Ks/Vs
    }

    // epilogue: normalize and write concat layout [b, s, h*DH + e], float4
    #pragma unroll
    for (int i = 0; i < 4; i++) {
        const float inv = 1.0f / lrow[i];
        const int sg = m0 + ty*4 + i;
        float4 o4 = make_float4(o[i][0]*inv, o[i][1]*inv, o[i][2]*inv, o[i][3]*inv);
        *(float4*)&g_att[((size_t)b * SS + sg) * DD + h * DHD + tx*4] = o4;
    }
}

// ---------------------------------------------------------------------------
// Kernel 3: output projection. out = att(4096x1024) @ Wo(1024x1024) + bo
// grid: (M/64, D/64), block: 256
// ---------------------------------------------------------------------------
__global__ __launch_bounds__(256) void out_kernel(
    const float* __restrict__ Wo, const float* __restrict__ bo, float* __restrict__ out)
{
    __shared__ float As[16][68];
    __shared__ float Bs[16][64];

    const int tid = threadIdx.x;
    const int ty = tid >> 4;
    const int tx = tid & 15;
    const int m0 = blockIdx.x * 64;
    const int n0 = blockIdx.y * 64;

    const int arow = tid >> 2, ac4 = tid & 3;
    const int brow = tid >> 4, bc4 = tid & 15;

    float acc[4][4] = {};

    for (int k0 = 0; k0 < DD; k0 += 16) {
        float4 av = *(const float4*)&g_att[(size_t)(m0 + arow) * DD + k0 + ac4 * 4];
        As[ac4*4+0][arow] = av.x;
        As[ac4*4+1][arow] = av.y;
        As[ac4*4+2][arow] = av.z;
        As[ac4*4+3][arow] = av.w;
        *(float4*)&Bs[brow][bc4*4] = *(const float4*)&Wo[(size_t)(k0 + brow) * DD + n0 + bc4 * 4];
        __syncthreads();
        #pragma unroll
        for (int kk = 0; kk < 16; kk++) {
            const float4 a4 = *(const float4*)&As[kk][ty*4];
            const float4 b4 = *(const float4*)&Bs[kk][tx*4];
            const float a[4] = {a4.x, a4.y, a4.z, a4.w};
            const float bb[4] = {b4.x, b4.y, b4.z, b4.w};
            #pragma unroll
            for (int i = 0; i < 4; i++)
                #pragma unroll
                for (int j = 0; j < 4; j++)
                    acc[i][j] += a[i] * bb[j];
        }
        __syncthreads();
    }

    const float4 bi = *(const float4*)&bo[n0 + tx*4];
    const float bv4[4] = {bi.x, bi.y, bi.z, bi.w};
    #pragma unroll
    for (int i = 0; i < 4; i++) {
        const int m = m0 + ty*4 + i;
        float4 o4 = make_float4(acc[i][0] + bv4[0], acc[i][1] + bv4[1],
                                acc[i][2] + bv4[2], acc[i][3] + bv4[3]);
        *(float4*)&out[(size_t)m * DD + n0 + tx*4] = o4;
    }
}

// ---------------------------------------------------------------------------
extern "C" void kernel_launch(void* const* d_in, const int* in_sizes, int n_in,
                              void* d_out, int out_size)
{
    (void)in_sizes; (void)n_in; (void)out_size;
    const float* x  = (const float*)d_in[0];
    const float* Wq = (const float*)d_in[1];
    const float* Wk = (const float*)d_in[2];
    const float* Wv = (const float*)d_in[3];
    const float* bq = (const float*)d_in[4];
    const float* bk = (const float*)d_in[5];
    const float* bv = (const float*)d_in[6];
    const float* Wo = (const float*)d_in[7];
    const float* bo = (const float*)d_in[8];
    float* out = (float*)d_out;

    // Device-function attribute set: not a stream op, legal under graph capture;
    // also already applied by the pre-capture correctness call.
    (void)cudaFuncSetAttribute(attn_kernel, cudaFuncAttributeMaxDynamicSharedMemorySize,
                               ATTN_SMEM_BYTES);

    qkv_kernel<<<dim3(MM/64, 3*HH), 256>>>(x, Wq, Wk, Wv, bq, bk, bv);
    attn_kernel<<<dim3(SS/64, HH, BB), 256, ATTN_SMEM_BYTES>>>();
    out_kernel<<<dim3(MM/64, DD/64), 256>>>(Wo, bo, out);
}

// round 3
// speedup vs baseline: 1.0095x; 1.0095x over previous
#include <cuda_runtime.h>
#include <math.h>

// Problem constants
#define BB 2
#define SS 2048
#define DD 1024
#define HH 16
#define DHD 64
#define MM (BB*SS)   // 4096

// Scratch (allocations forbidden; __device__ globals are the sanctioned path)
__device__ float g_q[(size_t)BB*HH*SS*DHD];   // [B,H,S,DH]
__device__ float g_k[(size_t)BB*HH*SS*DHD];
__device__ float g_v[(size_t)BB*HH*SS*DHD];
__device__ float g_att[(size_t)BB*SS*DD];     // [B,S,D]

// ---------------------------------------------------------------------------
// Kernel 1: fused QKV projection. BM=128, BN=64(=DH), BK=16, 128 threads,
// 8x8 micro-tile (rows ty*4+{0..3} and +64, cols tx*4+{0..3} and +32).
// All smem operand fetches: A broadcast across tx, B contiguous 128B/phase.
// grid: (M/128, 3*H), block: 128
// ---------------------------------------------------------------------------
__global__ __launch_bounds__(128) void qkv_kernel(
    const float* __restrict__ x,
    const float* __restrict__ Wq, const float* __restrict__ Wk, const float* __restrict__ Wv,
    const float* __restrict__ bq, const float* __restrict__ bk, const float* __restrict__ bv)
{
    __shared__ float As[16][132];  // transposed A [k][m], pad 132 (16B-aligned)
    __shared__ float Bs[16][64];

    const int tid = threadIdx.x;
    const int ty = tid >> 3;       // 0..15
    const int tx = tid & 7;        // 0..7
    const int m0 = blockIdx.x * 128;
    const int which = blockIdx.y / HH;
    const int h = blockIdx.y % HH;

    const float* W    = (which == 0) ? Wq : (which == 1) ? Wk : Wv;
    const float* bias = (which == 0) ? bq : (which == 1) ? bk : bv;
    float*       outp = (which == 0) ? g_q : (which == 1) ? g_k : g_v;
    W    += (size_t)h * DD * DHD;
    bias += h * DHD;

    float acc[2][2][4][4] = {};

    for (int k0 = 0; k0 < DD; k0 += 16) {
        // A: thread t owns gmem row m0+t, loads its 16 k-values, stores transposed
        {
            const float* xr = &x[(size_t)(m0 + tid) * DD + k0];
            #pragma unroll
            for (int c4 = 0; c4 < 4; c4++) {
                const float4 av = *(const float4*)&xr[c4*4];
                As[c4*4+0][tid] = av.x;
                As[c4*4+1][tid] = av.y;
                As[c4*4+2][tid] = av.z;
                As[c4*4+3][tid] = av.w;
            }
        }
        // B: 16x64; thread: row tid>>3, two float4 at (tid&7)*4 and +32
        {
            const int brow = tid >> 3, bc = tid & 7;
            const float* wr = &W[(size_t)(k0 + brow) * DHD];
            *(float4*)&Bs[brow][bc*4]      = *(const float4*)&wr[bc*4];
            *(float4*)&Bs[brow][bc*4 + 32] = *(const float4*)&wr[bc*4 + 32];
        }
        __syncthreads();
        #pragma unroll
        for (int kk = 0; kk < 16; kk++) {
            float a[2][4], b[2][4];
            { float4 t0 = *(const float4*)&As[kk][ty*4];
              a[0][0]=t0.x; a[0][1]=t0.y; a[0][2]=t0.z; a[0][3]=t0.w; }
            { float4 t1 = *(const float4*)&As[kk][ty*4 + 64];
              a[1][0]=t1.x; a[1][1]=t1.y; a[1][2]=t1.z; a[1][3]=t1.w; }
            { float4 t2 = *(const float4*)&Bs[kk][tx*4];
              b[0][0]=t2.x; b[0][1]=t2.y; b[0][2]=t2.z; b[0][3]=t2.w; }
            { float4 t3 = *(const float4*)&Bs[kk][tx*4 + 32];
              b[1][0]=t3.x; b[1][1]=t3.y; b[1][2]=t3.z; b[1][3]=t3.w; }
            #pragma unroll
            for (int ih = 0; ih < 2; ih++)
                #pragma unroll
                for (int jh = 0; jh < 2; jh++)
                    #pragma unroll
                    for (int i = 0; i < 4; i++)
                        #pragma unroll
                        for (int j = 0; j < 4; j++)
                            acc[ih][jh][i][j] += a[ih][i] * b[jh][j];
        }
        __syncthreads();
    }

    float bi[2][4];
    { float4 t = *(const float4*)&bias[tx*4];     bi[0][0]=t.x; bi[0][1]=t.y; bi[0][2]=t.z; bi[0][3]=t.w; }
    { float4 t = *(const float4*)&bias[tx*4+32];  bi[1][0]=t.x; bi[1][1]=t.y; bi[1][2]=t.z; bi[1][3]=t.w; }
    #pragma unroll
    for (int ih = 0; ih < 2; ih++)
        #pragma unroll
        for (int i = 0; i < 4; i++) {
            const int m = m0 + ty*4 + ih*64 + i;
            const int b_ = m >> 11;
            const int s  = m & (SS - 1);
            float* orow = &outp[(((size_t)b_ * HH + h) * SS + s) * DHD];
            #pragma unroll
            for (int jh = 0; jh < 2; jh++) {
                float4 o4 = make_float4(acc[ih][jh][i][0] + bi[jh][0],
                                        acc[ih][jh][i][1] + bi[jh][1],
                                        acc[ih][jh][i][2] + bi[jh][2],
                                        acc[ih][jh][i][3] + bi[jh][3]);
                *(float4*)&orow[tx*4 + jh*32] = o4;
            }
        }
}

// ---------------------------------------------------------------------------
// Kernel 2: flash attention per (b,h). Q-tile 128 rows, KV-tiles 64 keys.
// 128 threads, 8x8 micro-tiles in both matmuls. Q, K, P stored TRANSPOSED in
// smem so every inner-loop fetch is broadcast (row side) or contiguous (col side).
// grid: (S/128, H, B), block: 128, dynamic smem 102400 B
// ---------------------------------------------------------------------------
#define ATTN_SMEM_BYTES ((64*132 + 64*68 + 64*68 + 64*132) * 4)

__global__ __launch_bounds__(128) void attn_kernel()
{
    extern __shared__ float smem[];
    float (*Qt)[132] = reinterpret_cast<float(*)[132]>(smem);                       // [d][qrow]
    float (*Kt)[68]  = reinterpret_cast<float(*)[68]>(smem + 64*132);               // [d][key]
    float (*Vs)[68]  = reinterpret_cast<float(*)[68]>(smem + 64*132 + 64*68);       // [key][dh]
    float (*Pt)[132] = reinterpret_cast<float(*)[132]>(smem + 64*132 + 2*64*68);    // [key][qrow]

    const int tid = threadIdx.x;
    const int ty = tid >> 3;   // 0..15: rows ty*4+i, ty*4+64+i
    const int tx = tid & 7;    // 0..7 : cols tx*4+j, tx*4+32+j
    const int m0 = blockIdx.x * 128;
    const int h  = blockIdx.y;
    const int b  = blockIdx.z;

    const size_t head_base = ((size_t)b * HH + h) * SS;

    // Load Q tile transposed: thread t owns q-row m0+t
    {
        const float* qr = &g_q[(head_base + m0 + tid) * DHD];
        #pragma unroll
        for (int c4 = 0; c4 < 16; c4++) {
            const float4 qv = *(const float4*)&qr[c4*4];
            Qt[c4*4+0][tid] = qv.x;
            Qt[c4*4+1][tid] = qv.y;
            Qt[c4*4+2][tid] = qv.z;
            Qt[c4*4+3][tid] = qv.w;
        }
    }

    float o[2][2][4][4] = {};
    float mrow[2][4] = {{-1e30f,-1e30f,-1e30f,-1e30f},{-1e30f,-1e30f,-1e30f,-1e30f}};
    float lrow[2][4] = {};
    const float scale = 0.125f;  // 1/sqrt(64)

    __syncthreads();

    for (int kt = 0; kt < SS; kt += 64) {
        // Load K (transposed) and V: warps 0-1 -> K, warps 2-3 -> V
        if (tid < 64) {
            const float* kr = &g_k[(head_base + kt + tid) * DHD];
            #pragma unroll
            for (int c4 = 0; c4 < 16; c4++) {
                const float4 kv = *(const float4*)&kr[c4*4];
                Kt[c4*4+0][tid] = kv.x;
                Kt[c4*4+1][tid] = kv.y;
                Kt[c4*4+2][tid] = kv.z;
                Kt[c4*4+3][tid] = kv.w;
            }
        } else {
            const int r = tid - 64;
            const float* vr = &g_v[(head_base + kt + r) * DHD];
            #pragma unroll
            for (int c4 = 0; c4 < 16; c4++)
                *(float4*)&Vs[r][c4*4] = *(const float4*)&vr[c4*4];
        }
        __syncthreads();

        // S = Q @ K^T
        float sc[2][2][4][4] = {};
        #pragma unroll 4
        for (int d = 0; d < 64; d++) {
            float q[2][4], k[2][4];
            { float4 t0 = *(const float4*)&Qt[d][ty*4];
              q[0][0]=t0.x; q[0][1]=t0.y; q[0][2]=t0.z; q[0][3]=t0.w; }
            { float4 t1 = *(const float4*)&Qt[d][ty*4 + 64];
              q[1][0]=t1.x; q[1][1]=t1.y; q[1][2]=t1.z; q[1][3]=t1.w; }
            { float4 t2 = *(const float4*)&Kt[d][tx*4];
              k[0][0]=t2.x; k[0][1]=t2.y; k[0][2]=t2.z; k[0][3]=t2.w; }
            { float4 t3 = *(const float4*)&Kt[d][tx*4 + 32];
              k[1][0]=t3.x; k[1][1]=t3.y; k[1][2]=t3.z; k[1][3]=t3.w; }
            #pragma unroll
            for (int ih = 0; ih < 2; ih++)
                #pragma unroll
                for (int jh = 0; jh < 2; jh++)
                    #pragma unroll
                    for (int i = 0; i < 4; i++)
                        #pragma unroll
                        for (int j = 0; j < 4; j++)
                            sc[ih][jh][i][j] += q[ih][i] * k[jh][j];
        }

        // online softmax; each row's 64 keys live in the 8 lanes sharing ty
        // (lane = (ty&3)*8 + tx), so xor 1/2/4 reduces within the group.
        #pragma unroll
        for (int ih = 0; ih < 2; ih++)
            #pragma unroll
            for (int i = 0; i < 4; i++) {
                float mt = -1e30f;
                #pragma unroll
                for (int jh = 0; jh < 2; jh++)
                    #pragma unroll
                    for (int j = 0; j < 4; j++) {
                        sc[ih][jh][i][j] *= scale;
                        mt = fmaxf(mt, sc[ih][jh][i][j]);
                    }
                #pragma unroll
                for (int off = 4; off >= 1; off >>= 1)
                    mt = fmaxf(mt, __shfl_xor_sync(0xffffffffu, mt, off));
                const float mnew = fmaxf(mrow[ih][i], mt);
                const float corr = __expf(mrow[ih][i] - mnew);
                float ls = 0.f;
                #pragma unroll
                for (int jh = 0; jh < 2; jh++)
                    #pragma unroll
                    for (int j = 0; j < 4; j++) {
                        const float p = __expf(sc[ih][jh][i][j] - mnew);
                        sc[ih][jh][i][j] = p;
                        ls += p;
                    }
                #pragma unroll
                for (int off = 4; off >= 1; off >>= 1)
                    ls += __shfl_xor_sync(0xffffffffu, ls, off);
                lrow[ih][i] = lrow[ih][i] * corr + ls;
                mrow[ih][i] = mnew;
                #pragma unroll
                for (int jh = 0; jh < 2; jh++)
                    #pragma unroll
                    for (int j = 0; j < 4; j++)
                        o[ih][jh][i][j] *= corr;
            }

        __syncthreads();   // prior PV readers done before Pt rewrite (no-op first iter)
        #pragma unroll
        for (int ih = 0; ih < 2; ih++)
            #pragma unroll
            for (int jh = 0; jh < 2; jh++)
                #pragma unroll
                for (int i = 0; i < 4; i++)
                    #pragma unroll
                    for (int j = 0; j < 4; j++)
                        Pt[tx*4 + jh*32 + j][ty*4 + ih*64 + i] = sc[ih][jh][i][j];
        __syncthreads();

        // O += P @ V
        #pragma unroll 4
        for (int kk = 0; kk < 64; kk++) {
            float p[2][4], v[2][4];
            { float4 t0 = *(const float4*)&Pt[kk][ty*4];
              p[0][0]=t0.x; p[0][1]=t0.y; p[0][2]=t0.z; p[0][3]=t0.w; }
            { float4 t1 = *(const float4*)&Pt[kk][ty*4 + 64];
              p[1][0]=t1.x; p[1][1]=t1.y; p[1][2]=t1.z; p[1][3]=t1.w; }
            { float4 t2 = *(const float4*)&Vs[kk][tx*4];
              v[0][0]=t2.x; v[0][1]=t2.y; v[0][2]=t2.z; v[0][3]=t2.w; }
            { float4 t3 = *(const float4*)&Vs[kk][tx*4 + 32];
              v[1][0]=t3.x; v[1][1]=t3.y; v[1][2]=t3.z; v[1][3]=t3.w; }
            #pragma unroll
            for (int ih = 0; ih < 2; ih++)
                #pragma unroll
                for (int jh = 0; jh < 2; jh++)
                    #pragma unroll
                    for (int i = 0; i < 4; i++)
                        #pragma unroll
                        for (int j = 0; j < 4; j++)
                            o[ih][jh][i][j] += p[ih][i] * v[jh][j];
        }
        __syncthreads();   // before next tile overwrites Kt/Vs
    }

    // epilogue: normalize, write concat layout [b, s, h*DH + e]
    #pragma unroll
    for (int ih = 0; ih < 2; ih++)
        #pragma unroll
        for (int i = 0; i < 4; i++) {
            const float inv = 1.0f / lrow[ih][i];
            const int sg = m0 + ty*4 + ih*64 + i;
            float* orow = &g_att[((size_t)b * SS + sg) * DD + h * DHD];
            #pragma unroll
            for (int jh = 0; jh < 2; jh++) {
                float4 o4 = make_float4(o[ih][jh][i][0]*inv, o[ih][jh][i][1]*inv,
                                        o[ih][jh][i][2]*inv, o[ih][jh][i][3]*inv);
                *(float4*)&orow[tx*4 + jh*32] = o4;
            }
        }
}

// ---------------------------------------------------------------------------
// Kernel 3: output projection. BM=128, BN=128, BK=16, 256 threads, 8x8 micro.
// grid: (M/128, D/128), block: 256
// ---------------------------------------------------------------------------
__global__ __launch_bounds__(256) void out_kernel(
    const float* __restrict__ Wo, const float* __restrict__ bo, float* __restrict__ out)
{
    __shared__ float As[16][132];
    __shared__ float Bs[16][128];

    const int tid = threadIdx.x;
    const int ty = tid >> 4;   // 0..15: rows ty*4+i, +64
    const int tx = tid & 15;   // 0..15: cols tx*4+j, +64
    const int m0 = blockIdx.x * 128;
    const int n0 = blockIdx.y * 128;

    float acc[2][2][4][4] = {};

    for (int k0 = 0; k0 < DD; k0 += 16) {
        // A: 2 threads per row, each 8 k-values, stored transposed
        {
            const int arow = tid >> 1, ah = tid & 1;
            const float* ar = &g_att[(size_t)(m0 + arow) * DD + k0 + ah*8];
            #pragma unroll
            for (int c4 = 0; c4 < 2; c4++) {
                const float4 av = *(const float4*)&ar[c4*4];
                As[ah*8 + c4*4 + 0][arow] = av.x;
                As[ah*8 + c4*4 + 1][arow] = av.y;
                As[ah*8 + c4*4 + 2][arow] = av.z;
                As[ah*8 + c4*4 + 3][arow] = av.w;
            }
        }
        // B: 16x128; thread: row tid>>4, float4 at (tid&15)*4 and +64
        {
            const int brow = tid >> 4, bc = tid & 15;
            const float* wr = &Wo[(size_t)(k0 + brow) * DD + n0];
            *(float4*)&Bs[brow][bc*4]      = *(const float4*)&wr[bc*4];
            *(float4*)&Bs[brow][bc*4 + 64] = *(const float4*)&wr[bc*4 + 64];
        }
        __syncthreads();
        #pragma unroll
        for (int kk = 0; kk < 16; kk++) {
            float a[2][4], b[2][4];
            { float4 t0 = *(const float4*)&As[kk][ty*4];
              a[0][0]=t0.x; a[0][1]=t0.y; a[0][2]=t0.z; a[0][3]=t0.w; }
            { float4 t1 = *(const float4*)&As[kk][ty*4 + 64];
              a[1][0]=t1.x; a[1][1]=t1.y; a[1][2]=t1.z; a[1][3]=t1.w; }
            { float4 t2 = *(const float4*)&Bs[kk][tx*4];
              b[0][0]=t2.x; b[0][1]=t2.y; b[0][2]=t2.z; b[0][3]=t2.w; }
            { float4 t3 = *(const float4*)&Bs[kk][tx*4 + 64];
              b[1][0]=t3.x; b[1][1]=t3.y; b[1][2]=t3.z; b[1][3]=t3.w; }
            #pragma unroll
            for (int ih = 0; ih < 2; ih++)
                #pragma unroll
                for (int jh = 0; jh < 2; jh++)
                    #pragma unroll
                    for (int i = 0; i < 4; i++)
                        #pragma unroll
                        for (int j = 0; j < 4; j++)
                            acc[ih][jh][i][j] += a[ih][i] * b[jh][j];
        }
        __syncthreads();
    }

    float bi[2][4];
    { float4 t = *(const float4*)&bo[n0 + tx*4];      bi[0][0]=t.x; bi[0][1]=t.y; bi[0][2]=t.z; bi[0][3]=t.w; }
    { float4 t = *(const float4*)&bo[n0 + tx*4 + 64]; bi[1][0]=t.x; bi[1][1]=t.y; bi[1][2]=t.z; bi[1][3]=t.w; }
    #pragma unroll
    for (int ih = 0; ih < 2; ih++)
        #pragma unroll
        for (int i = 0; i < 4; i++) {
            const int m = m0 + ty*4 + ih*64 + i;
            #pragma unroll
            for (int jh = 0; jh < 2; jh++) {
                float4 o4 = make_float4(acc[ih][jh][i][0] + bi[jh][0],
                                        acc[ih][jh][i][1] + bi[jh][1],
                                        acc[ih][jh][i][2] + bi[jh][2],
                                        acc[ih][jh][i][3] + bi[jh][3]);
                *(float4*)&out[(size_t)m * DD + n0 + tx*4 + jh*64] = o4;
            }
        }
}

// ---------------------------------------------------------------------------
extern "C" void kernel_launch(void* const* d_in, const int* in_sizes, int n_in,
                              void* d_out, int out_size)
{
    (void)in_sizes; (void)n_in; (void)out_size;
    const float* x  = (const float*)d_in[0];
    const float* Wq = (const float*)d_in[1];
    const float* Wk = (const float*)d_in[2];
    const float* Wv = (const float*)d_in[3];
    const float* bq = (const float*)d_in[4];
    const float* bk = (const float*)d_in[5];
    const float* bv = (const float*)d_in[6];
    const float* Wo = (const float*)d_in[7];
    const float* bo = (const float*)d_in[8];
    float* out = (float*)d_out;

    (void)cudaFuncSetAttribute(attn_kernel, cudaFuncAttributeMaxDynamicSharedMemorySize,
                               ATTN_SMEM_BYTES);

    qkv_kernel<<<dim3(MM/128, 3*HH), 128>>>(x, Wq, Wk, Wv, bq, bk, bv);
    attn_kernel<<<dim3(SS/128, HH, BB), 128, ATTN_SMEM_BYTES>>>();
    out_kernel<<<dim3(MM/128, DD/128), 256>>>(Wo, bo, out);
}

// round 4
// speedup vs baseline: 1.1559x; 1.1451x over previous
#include <cuda_runtime.h>
#include <math.h>
#include <stdint.h>

// Problem constants
#define BB 2
#define SS 2048
#define DD 1024
#define HH 16
#define DHD 64
#define MM (BB*SS)   // 4096

// Scratch (allocations forbidden; __device__ globals are the sanctioned path)
__device__ float g_q[(size_t)BB*HH*SS*DHD];   // [B,H,S,DH]
__device__ float g_k[(size_t)BB*HH*SS*DHD];
__device__ float g_v[(size_t)BB*HH*SS*DHD];
__device__ float g_att[(size_t)BB*SS*DD];     // [B,S,D]

// ---------------------------------------------------------------------------
// tf32 helpers
// ---------------------------------------------------------------------------
__device__ __forceinline__ uint32_t f2tf(float x) {
    uint32_t r; asm("cvt.rna.tf32.f32 %0, %1;" : "=r"(r) : "f"(x)); return r;
}
// error-free-ish split: x = hi + lo with hi,lo both tf32-exact (drops ~2^-23)
__device__ __forceinline__ void split_tf(float x, uint32_t& hi, uint32_t& lo) {
    hi = f2tf(x);
    lo = f2tf(x - __uint_as_float(hi));
}
// D += A(16x8,row) * B(8x8,col), tf32 inputs, fp32 accum
__device__ __forceinline__ void mma8(float* d, const uint32_t* a, uint32_t b0, uint32_t b1) {
    asm("mma.sync.aligned.m16n8k8.row.col.f32.tf32.tf32.f32 "
        "{%0,%1,%2,%3}, {%4,%5,%6,%7}, {%8,%9}, {%0,%1,%2,%3};"
        : "+f"(d[0]), "+f"(d[1]), "+f"(d[2]), "+f"(d[3])
        : "r"(a[0]), "r"(a[1]), "r"(a[2]), "r"(a[3]), "r"(b0), "r"(b1));
}

// ---------------------------------------------------------------------------
// Kernel 1: fused QKV projection, 3xTF32 tensor GEMM.
// C[4096,64] per (which,h). Block tile M=128,N=64,BK=16; 8 warps, warp = m16 x n64.
// smem: A transposed [k][m] stride 136 (banks 8t+g distinct), B [k][n] stride 72.
// grid (32, 48), block 256
// ---------------------------------------------------------------------------
__global__ __launch_bounds__(256, 2) void qkv_kernel(
    const float* __restrict__ x,
    const float* __restrict__ Wq, const float* __restrict__ Wk, const float* __restrict__ Wv,
    const float* __restrict__ bq, const float* __restrict__ bk, const float* __restrict__ bv)
{
    __shared__ uint32_t Ahi[16][136], Alo[16][136];
    __shared__ uint32_t Bhi[16][72],  Blo[16][72];

    const int tid  = threadIdx.x;
    const int lane = tid & 31, warp = tid >> 5;
    const int g = lane >> 2, t = lane & 3;
    const int wm = warp * 16;
    const int m0 = blockIdx.x * 128;
    const int which = blockIdx.y / HH, h = blockIdx.y % HH;

    const float* W    = (which == 0) ? Wq : (which == 1) ? Wk : Wv;
    const float* bias = (which == 0) ? bq : (which == 1) ? bk : bv;
    float*       outp = (which == 0) ? g_q : (which == 1) ? g_k : g_v;
    W    += (size_t)h * DD * DHD;
    bias += h * DHD;

    float acc[8][4] = {};

    const int arow = tid >> 1, aseg = (tid & 1) * 8;   // A: 128 rows x 2 half-rows of 8
    const int brow = tid >> 4, bcol = (tid & 15) * 4;  // B: 16 rows x 16 float4

    for (int k0 = 0; k0 < DD; k0 += 16) {
        {   // stage + split A (x)
            const float* src = &x[(size_t)(m0 + arow) * DD + k0 + aseg];
            const float4 v0 = *(const float4*)&src[0];
            const float4 v1 = *(const float4*)&src[4];
            const float vv[8] = {v0.x,v0.y,v0.z,v0.w,v1.x,v1.y,v1.z,v1.w};
            #pragma unroll
            for (int i = 0; i < 8; i++) {
                uint32_t hi, lo; split_tf(vv[i], hi, lo);
                Ahi[aseg+i][arow] = hi; Alo[aseg+i][arow] = lo;
            }
        }
        {   // stage + split B (W)
            const float* src = &W[(size_t)(k0 + brow) * DHD + bcol];
            const float4 v0 = *(const float4*)src;
            const float vv[4] = {v0.x,v0.y,v0.z,v0.w};
            #pragma unroll
            for (int i = 0; i < 4; i++) {
                uint32_t hi, lo; split_tf(vv[i], hi, lo);
                Bhi[brow][bcol+i] = hi; Blo[brow][bcol+i] = lo;
            }
        }
        __syncthreads();
        #pragma unroll
        for (int ks = 0; ks < 2; ks++) {
            const int kb = ks * 8;
            uint32_t ah[4], al[4];
            ah[0] = Ahi[kb+t  ][wm+g];   al[0] = Alo[kb+t  ][wm+g];
            ah[1] = Ahi[kb+t  ][wm+g+8]; al[1] = Alo[kb+t  ][wm+g+8];
            ah[2] = Ahi[kb+t+4][wm+g];   al[2] = Alo[kb+t+4][wm+g];
            ah[3] = Ahi[kb+t+4][wm+g+8]; al[3] = Alo[kb+t+4][wm+g+8];
            #pragma unroll
            for (int nt = 0; nt < 8; nt++) {
                const uint32_t bh0 = Bhi[kb+t  ][nt*8+g], bl0 = Blo[kb+t  ][nt*8+g];
                const uint32_t bh1 = Bhi[kb+t+4][nt*8+g], bl1 = Blo[kb+t+4][nt*8+g];
                mma8(acc[nt], ah, bh0, bh1);
                mma8(acc[nt], ah, bl0, bl1);
                mma8(acc[nt], al, bh0, bh1);
            }
        }
        __syncthreads();
    }

    #pragma unroll
    for (int nt = 0; nt < 8; nt++) {
        const int n = nt*8 + 2*t;
        const float b0 = bias[n], b1 = bias[n+1];
        const int m_a = m0 + wm + g, m_b = m_a + 8;
        {
            const int bb_ = m_a >> 11, s = m_a & (SS-1);
            const float2 o = make_float2(acc[nt][0] + b0, acc[nt][1] + b1);
            *(float2*)&outp[(((size_t)bb_*HH + h)*SS + s)*DHD + n] = o;
        }
        {
            const int bb_ = m_b >> 11, s = m_b & (SS-1);
            const float2 o = make_float2(acc[nt][2] + b0, acc[nt][3] + b1);
            *(float2*)&outp[(((size_t)bb_*HH + h)*SS + s)*DHD + n] = o;
        }
    }
}

// ---------------------------------------------------------------------------
// Kernel 2: flash attention, 3xTF32 tensor path.
// Block: 256 thr, Q-tile 128 rows (warp w -> rows w*16..+15), KV-tile 64.
// Qs fp32 (pre-scaled by 1/8), split per-fragment; K/V split at staging.
// P re-fragmented from S accumulators via intra-quad shfl (no smem round-trip).
// smem 108544 B -> 2 blocks/SM. grid (16, 16, 2)
// ---------------------------------------------------------------------------
#define ATT_SMEM_BYTES ((64*136 + 4*64*72) * 4)

__global__ __launch_bounds__(256, 2) void attn_kernel()
{
    extern __shared__ float smem[];
    float    (*Qs)[136] = reinterpret_cast<float(*)[136]>(smem);                       // [d][qrow]
    uint32_t (*Khi)[72] = reinterpret_cast<uint32_t(*)[72]>(smem + 64*136);            // [d][key]
    uint32_t (*Klo)[72] = reinterpret_cast<uint32_t(*)[72]>(smem + 64*136 + 64*72);
    uint32_t (*Vhi)[72] = reinterpret_cast<uint32_t(*)[72]>(smem + 64*136 + 2*64*72);  // [key][dh]
    uint32_t (*Vlo)[72] = reinterpret_cast<uint32_t(*)[72]>(smem + 64*136 + 3*64*72);

    const int tid  = threadIdx.x;
    const int lane = tid & 31, warp = tid >> 5;
    const int g = lane >> 2, t = lane & 3;
    const int wm = warp * 16;
    const int qbase = blockIdx.x * 128;
    const int h = blockIdx.y, b = blockIdx.z;
    const size_t head_base = ((size_t)b * HH + h) * SS;

    {   // load Q (once), pre-scaled by 1/sqrt(DH)=0.125, transposed [d][qrow]
        const int row = tid >> 1, seg = (tid & 1) * 32;
        const float* src = &g_q[(head_base + qbase + row) * DHD + seg];
        #pragma unroll
        for (int c = 0; c < 8; c++) {
            const float4 v = *(const float4*)&src[c*4];
            Qs[seg+c*4+0][row] = v.x * 0.125f;
            Qs[seg+c*4+1][row] = v.y * 0.125f;
            Qs[seg+c*4+2][row] = v.z * 0.125f;
            Qs[seg+c*4+3][row] = v.w * 0.125f;
        }
    }

    float O[8][4] = {};
    float mx0 = -1e30f, mx1 = -1e30f, l0 = 0.f, l1 = 0.f;

    for (int kt = 0; kt < SS; kt += 64) {
        {   // stage K (transposed+split) and V (split)
            const int key = tid >> 2, seg = (tid & 3) * 16;
            const float* ksrc = &g_k[(head_base + kt + key) * DHD + seg];
            #pragma unroll
            for (int c = 0; c < 4; c++) {
                const float4 v = *(const float4*)&ksrc[c*4];
                const float vv[4] = {v.x,v.y,v.z,v.w};
                #pragma unroll
                for (int i = 0; i < 4; i++) {
                    uint32_t hi, lo; split_tf(vv[i], hi, lo);
                    Khi[seg+c*4+i][key] = hi; Klo[seg+c*4+i][key] = lo;
                }
            }
            const float* vsrc = &g_v[(head_base + kt + key) * DHD + seg];
            #pragma unroll
            for (int c = 0; c < 4; c++) {
                const float4 v = *(const float4*)&vsrc[c*4];
                uint32_t h4[4], l4[4];
                split_tf(v.x, h4[0], l4[0]); split_tf(v.y, h4[1], l4[1]);
                split_tf(v.z, h4[2], l4[2]); split_tf(v.w, h4[3], l4[3]);
                *(uint4*)&Vhi[key][seg+c*4] = make_uint4(h4[0],h4[1],h4[2],h4[3]);
                *(uint4*)&Vlo[key][seg+c*4] = make_uint4(l4[0],l4[1],l4[2],l4[3]);
            }
        }
        __syncthreads();

        // ---- S = (Q/8) @ K^T ----
        float S[8][4] = {};
        #pragma unroll
        for (int kd = 0; kd < 8; kd++) {
            const int kb = kd * 8;
            uint32_t ah[4], al[4];
            split_tf(Qs[kb+t  ][wm+g],   ah[0], al[0]);
            split_tf(Qs[kb+t  ][wm+g+8], ah[1], al[1]);
            split_tf(Qs[kb+t+4][wm+g],   ah[2], al[2]);
            split_tf(Qs[kb+t+4][wm+g+8], ah[3], al[3]);
            #pragma unroll
            for (int nt = 0; nt < 8; nt++) {
                const uint32_t bh0 = Khi[kb+t  ][nt*8+g], bl0 = Klo[kb+t  ][nt*8+g];
                const uint32_t bh1 = Khi[kb+t+4][nt*8+g], bl1 = Klo[kb+t+4][nt*8+g];
                mma8(S[nt], ah, bh0, bh1);
                mma8(S[nt], ah, bl0, bl1);
                mma8(S[nt], al, bh0, bh1);
            }
        }

        // ---- online softmax (row g -> regs 0,1 ; row g+8 -> regs 2,3) ----
        float mt0 = -1e30f, mt1 = -1e30f;
        #pragma unroll
        for (int nt = 0; nt < 8; nt++) {
            mt0 = fmaxf(mt0, fmaxf(S[nt][0], S[nt][1]));
            mt1 = fmaxf(mt1, fmaxf(S[nt][2], S[nt][3]));
        }
        #pragma unroll
        for (int off = 2; off >= 1; off >>= 1) {
            mt0 = fmaxf(mt0, __shfl_xor_sync(0xffffffffu, mt0, off));
            mt1 = fmaxf(mt1, __shfl_xor_sync(0xffffffffu, mt1, off));
        }
        const float mn0 = fmaxf(mx0, mt0), mn1 = fmaxf(mx1, mt1);
        const float c0 = __expf(mx0 - mn0), c1 = __expf(mx1 - mn1);
        float ls0 = 0.f, ls1 = 0.f;
        #pragma unroll
        for (int nt = 0; nt < 8; nt++) {
            S[nt][0] = __expf(S[nt][0] - mn0); ls0 += S[nt][0];
            S[nt][1] = __expf(S[nt][1] - mn0); ls0 += S[nt][1];
            S[nt][2] = __expf(S[nt][2] - mn1); ls1 += S[nt][2];
            S[nt][3] = __expf(S[nt][3] - mn1); ls1 += S[nt][3];
        }
        #pragma unroll
        for (int off = 2; off >= 1; off >>= 1) {
            ls0 += __shfl_xor_sync(0xffffffffu, ls0, off);
            ls1 += __shfl_xor_sync(0xffffffffu, ls1, off);
        }
        l0 = l0 * c0 + ls0;  l1 = l1 * c1 + ls1;
        mx0 = mn0;           mx1 = mn1;
        #pragma unroll
        for (int nt = 0; nt < 8; nt++) {
            O[nt][0] *= c0; O[nt][1] *= c0;
            O[nt][2] *= c1; O[nt][3] *= c1;
        }

        // ---- O += P @ V ----
        // P A-frag (row g/g+8, key col t / t+4 of k-tile kq) gathered from the
        // S C-frag (cols 2t', 2t'+1) held within the same lane-quad via shfl.
        const int src1 = (lane & ~3) | (t >> 1);   // holder of cols t
        const int src2 = src1 + 2;                 // holder of cols t+4
        const bool odd = (t & 1);
        #pragma unroll
        for (int kq = 0; kq < 8; kq++) {
            const float p0a = __shfl_sync(0xffffffffu, S[kq][0], src1);
            const float p0b = __shfl_sync(0xffffffffu, S[kq][1], src1);
            const float p1a = __shfl_sync(0xffffffffu, S[kq][2], src1);
            const float p1b = __shfl_sync(0xffffffffu, S[kq][3], src1);
            const float p2a = __shfl_sync(0xffffffffu, S[kq][0], src2);
            const float p2b = __shfl_sync(0xffffffffu, S[kq][1], src2);
            const float p3a = __shfl_sync(0xffffffffu, S[kq][2], src2);
            const float p3b = __shfl_sync(0xffffffffu, S[kq][3], src2);
            const float pf[4] = { odd ? p0b : p0a, odd ? p1b : p1a,
                                  odd ? p2b : p2a, odd ? p3b : p3a };
            uint32_t ah[4], al[4];
            #pragma unroll
            for (int i = 0; i < 4; i++) split_tf(pf[i], ah[i], al[i]);
            #pragma unroll
            for (int nt = 0; nt < 8; nt++) {
                const uint32_t bh0 = Vhi[kq*8+t  ][nt*8+g], bl0 = Vlo[kq*8+t  ][nt*8+g];
                const uint32_t bh1 = Vhi[kq*8+t+4][nt*8+g], bl1 = Vlo[kq*8+t+4][nt*8+g];
                mma8(O[nt], ah, bh0, bh1);
                mma8(O[nt], ah, bl0, bl1);
                mma8(O[nt], al, bh0, bh1);
            }
        }
        __syncthreads();   // before next tile overwrites K/V
    }

    // epilogue: normalize, write concat layout [b, s, h*DH + e]
    const float i0 = 1.f / l0, i1 = 1.f / l1;
    #pragma unroll
    for (int nt = 0; nt < 8; nt++) {
        const int n = nt*8 + 2*t;
        const int sa = qbase + wm + g, sb = sa + 8;
        const float2 oa = make_float2(O[nt][0]*i0, O[nt][1]*i0);
        const float2 ob = make_float2(O[nt][2]*i1, O[nt][3]*i1);
        *(float2*)&g_att[((size_t)b*SS + sa)*DD + h*DHD + n] = oa;
        *(float2*)&g_att[((size_t)b*SS + sb)*DD + h*DHD + n] = ob;
    }
}

// ---------------------------------------------------------------------------
// Kernel 3: output projection, 3xTF32 tensor GEMM.
// out[4096,1024] = att @ Wo + bo. Block tile M=128,N=64,BK=16; grid (32, 16)
// ---------------------------------------------------------------------------
__global__ __launch_bounds__(256, 2) void out_kernel(
    const float* __restrict__ Wo, const float* __restrict__ bo, float* __restrict__ out)
{
    __shared__ uint32_t Ahi[16][136], Alo[16][136];
    __shared__ uint32_t Bhi[16][72],  Blo[16][72];

    const int tid  = threadIdx.x;
    const int lane = tid & 31, warp = tid >> 5;
    const int g = lane >> 2, t = lane & 3;
    const int wm = warp * 16;
    const int m0 = blockIdx.x * 128;
    const int n0 = blockIdx.y * 64;

    float acc[8][4] = {};

    const int arow = tid >> 1, aseg = (tid & 1) * 8;
    const int brow = tid >> 4, bcol = (tid & 15) * 4;

    for (int k0 = 0; k0 < DD; k0 += 16) {
        {
            const float* src = &g_att[(size_t)(m0 + arow) * DD + k0 + aseg];
            const float4 v0 = *(const float4*)&src[0];
            const float4 v1 = *(const float4*)&src[4];
            const float vv[8] = {v0.x,v0.y,v0.z,v0.w,v1.x,v1.y,v1.z,v1.w};
            #pragma unroll
            for (int i = 0; i < 8; i++) {
                uint32_t hi, lo; split_tf(vv[i], hi, lo);
                Ahi[aseg+i][arow] = hi; Alo[aseg+i][arow] = lo;
            }
        }
        {
            const float* src = &Wo[(size_t)(k0 + brow) * DD + n0 + bcol];
            const float4 v0 = *(const float4*)src;
            const float vv[4] = {v0.x,v0.y,v0.z,v0.w};
            #pragma unroll
            for (int i = 0; i < 4; i++) {
                uint32_t hi, lo; split_tf(vv[i], hi, lo);
                Bhi[brow][bcol+i] = hi; Blo[brow][bcol+i] = lo;
            }
        }
        __syncthreads();
        #pragma unroll
        for (int ks = 0; ks < 2; ks++) {
            const int kb = ks * 8;
            uint32_t ah[4], al[4];
            ah[0] = Ahi[kb+t  ][wm+g];   al[0] = Alo[kb+t  ][wm+g];
            ah[1] = Ahi[kb+t  ][wm+g+8]; al[1] = Alo[kb+t  ][wm+g+8];
            ah[2] = Ahi[kb+t+4][wm+g];   al[2] = Alo[kb+t+4][wm+g];
            ah[3] = Ahi[kb+t+4][wm+g+8]; al[3] = Alo[kb+t+4][wm+g+8];
            #pragma unroll
            for (int nt = 0; nt < 8; nt++) {
                const uint32_t bh0 = Bhi[kb+t  ][nt*8+g], bl0 = Blo[kb+t  ][nt*8+g];
                const uint32_t bh1 = Bhi[kb+t+4][nt*8+g], bl1 = Blo[kb+t+4][nt*8+g];
                mma8(acc[nt], ah, bh0, bh1);
                mma8(acc[nt], ah, bl0, bl1);
                mma8(acc[nt], al, bh0, bh1);
            }
        }
        __syncthreads();
    }

    #pragma unroll
    for (int nt = 0; nt < 8; nt++) {
        const int n = n0 + nt*8 + 2*t;
        const float b0 = bo[n], b1 = bo[n+1];
        const int m_a = m0 + wm + g, m_b = m_a + 8;
        const float2 oa = make_float2(acc[nt][0] + b0, acc[nt][1] + b1);
        const float2 ob = make_float2(acc[nt][2] + b0, acc[nt][3] + b1);
        *(float2*)&out[(size_t)m_a * DD + n] = oa;
        *(float2*)&out[(size_t)m_b * DD + n] = ob;
    }
}

// ---------------------------------------------------------------------------
extern "C" void kernel_launch(void* const* d_in, const int* in_sizes, int n_in,
                              void* d_out, int out_size)
{
    (void)in_sizes; (void)n_in; (void)out_size;
    const float* x  = (const float*)d_in[0];
    const float* Wq = (const float*)d_in[1];
    const float* Wk = (const float*)d_in[2];
    const float* Wv = (const float*)d_in[3];
    const float* bq = (const float*)d_in[4];
    const float* bk = (const float*)d_in[5];
    const float* bv = (const float*)d_in[6];
    const float* Wo = (const float*)d_in[7];
    const float* bo = (const float*)d_in[8];
    float* out = (float*)d_out;

    (void)cudaFuncSetAttribute(attn_kernel, cudaFuncAttributeMaxDynamicSharedMemorySize,
                               ATT_SMEM_BYTES);

    qkv_kernel<<<dim3(MM/128, 3*HH), 256>>>(x, Wq, Wk, Wv, bq, bk, bv);
    attn_kernel<<<dim3(SS/128, HH, BB), 256, ATT_SMEM_BYTES>>>();
    out_kernel<<<dim3(MM/128, DD/64), 256>>>(Wo, bo, out);
}

// round 5
// speedup vs baseline: 1.6078x; 1.3909x over previous
#include <cuda_runtime.h>
#include <cuda_bf16.h>
#include <math.h>
#include <stdint.h>

#define BB 2
#define SS 2048
#define DD 1024
#define HH 16
#define DHD 64
#define MM (BB*SS)   // 4096

// Scratch
__device__ float g_q[(size_t)BB*HH*SS*DHD];
__device__ float g_k[(size_t)BB*HH*SS*DHD];
__device__ float g_v[(size_t)BB*HH*SS*DHD];
__device__ float g_att[(size_t)BB*SS*DD];

// ---------------------------------------------------------------------------
// bf16 helpers
// ---------------------------------------------------------------------------
// split x0,x1 into (hi,lo) bf16x2 packs; low 16 bits = x0 (first k element)
__device__ __forceinline__ void split_pair(float x0, float x1, uint32_t& hi, uint32_t& lo) {
    __nv_bfloat16 h0 = __float2bfloat16_rn(x0);
    __nv_bfloat16 h1 = __float2bfloat16_rn(x1);
    __nv_bfloat16 l0 = __float2bfloat16_rn(x0 - __bfloat162float(h0));
    __nv_bfloat16 l1 = __float2bfloat16_rn(x1 - __bfloat162float(h1));
    hi = ((uint32_t)__bfloat16_as_ushort(h1) << 16) | (uint32_t)__bfloat16_as_ushort(h0);
    lo = ((uint32_t)__bfloat16_as_ushort(l1) << 16) | (uint32_t)__bfloat16_as_ushort(l0);
}
// D += A(16x16,row) * B(16x8,col), bf16 in, fp32 accum
__device__ __forceinline__ void mma16(float* d, const uint32_t* a, uint32_t b0, uint32_t b1) {
    asm volatile("mma.sync.aligned.m16n8k16.row.col.f32.bf16.bf16.f32 "
        "{%0,%1,%2,%3}, {%4,%5,%6,%7}, {%8,%9}, {%0,%1,%2,%3};"
        : "+f"(d[0]), "+f"(d[1]), "+f"(d[2]), "+f"(d[3])
        : "r"(a[0]), "r"(a[1]), "r"(a[2]), "r"(a[3]), "r"(b0), "r"(b1));
}

// Fragment-order smem indices
// A-frag: [split][kb][warpblock][lane][reg]  (LDS.128 per lane)
#define AFI(s,kb,wb,l,r) (((((s)*2+(kb))*8+(wb))*32+(l))*4+(r))
// B-frag: [split][kb][lane][idx(nt*2+reg)], stride 20 words (bank-spread pad)
#define BFI(s,kb,l,i)    ((((s)*2+(kb))*32+(l))*20+(i))

// ---------------------------------------------------------------------------
// Kernel 1: fused QKV projection. BM=128, N=64, BK=32, 256 thr, 8 warps (m16 x n64).
// grid (32, 48)
// ---------------------------------------------------------------------------
__global__ __launch_bounds__(256) void qkv_kernel(
    const float* __restrict__ x,
    const float* __restrict__ Wq, const float* __restrict__ Wk, const float* __restrict__ Wv,
    const float* __restrict__ bq, const float* __restrict__ bk, const float* __restrict__ bv)
{
    __shared__ uint32_t AF[2*2*8*32*4];   // 16 KB
    __shared__ uint32_t BF[2*2*32*20];    // 10 KB

    const int tid  = threadIdx.x;
    const int lane = tid & 31, warp = tid >> 5;
    const int m0 = blockIdx.x * 128;
    const int which = blockIdx.y / HH, h = blockIdx.y % HH;

    const float* W    = (which == 0) ? Wq : (which == 1) ? Wk : Wv;
    const float* bias = (which == 0) ? bq : (which == 1) ? bk : bv;
    float*       outp = (which == 0) ? g_q : (which == 1) ? g_k : g_v;
    W    += (size_t)h * DD * DHD;
    bias += h * DHD;

    float acc[8][4] = {};

    // staging roles
    const int ar = tid >> 1, akb = tid & 1;          // A: row m0+ar, k-half akb
    const int awb = ar >> 4, ag = ar & 7, arh = (ar >> 3) & 1;
    const int kp = tid >> 4, n4 = (tid & 15) * 4;    // B: k-pair kp, cols n4..n4+3
    const int kbB = kp >> 3, regB = (kp >> 2) & 1, tB = kp & 3;

    float4 pa[4]; float4 pb0, pb1;
    {
        const float* xr = &x[(size_t)(m0 + ar) * DD + akb*16];
        #pragma unroll
        for (int c = 0; c < 4; c++) pa[c] = *(const float4*)&xr[c*4];
        pb0 = *(const float4*)&W[(size_t)(2*kp  ) * DHD + n4];
        pb1 = *(const float4*)&W[(size_t)(2*kp+1) * DHD + n4];
    }

    for (int k0 = 0; k0 < DD; k0 += 32) {
        // ---- split + store staged chunk ----
        #pragma unroll
        for (int c4 = 0; c4 < 4; c4++) {
            const int cc = c4*4, chalf = cc >> 3, t0 = (cc & 7) >> 1;
            const int reg = arh + 2*chalf, ln = ag*4 + t0;
            uint32_t h0,l0,h1,l1;
            split_pair(pa[c4].x, pa[c4].y, h0, l0);
            split_pair(pa[c4].z, pa[c4].w, h1, l1);
            AF[AFI(0,akb,awb,ln,  reg)] = h0;
            AF[AFI(0,akb,awb,ln+1,reg)] = h1;
            AF[AFI(1,akb,awb,ln,  reg)] = l0;
            AF[AFI(1,akb,awb,ln+1,reg)] = l1;
        }
        {
            const float w0[4] = {pb0.x,pb0.y,pb0.z,pb0.w};
            const float w1[4] = {pb1.x,pb1.y,pb1.z,pb1.w};
            #pragma unroll
            for (int j = 0; j < 4; j++) {
                const int n = n4 + j, gn = n & 7, nt = n >> 3;
                uint32_t hh, ll;
                split_pair(w0[j], w1[j], hh, ll);
                BF[BFI(0,kbB,gn*4+tB,nt*2+regB)] = hh;
                BF[BFI(1,kbB,gn*4+tB,nt*2+regB)] = ll;
            }
        }
        __syncthreads();
        // ---- prefetch next chunk ----
        if (k0 + 32 < DD) {
            const float* xr = &x[(size_t)(m0 + ar) * DD + k0 + 32 + akb*16];
            #pragma unroll
            for (int c = 0; c < 4; c++) pa[c] = *(const float4*)&xr[c*4];
            pb0 = *(const float4*)&W[(size_t)(k0+32 + 2*kp  ) * DHD + n4];
            pb1 = *(const float4*)&W[(size_t)(k0+32 + 2*kp+1) * DHD + n4];
        }
        // ---- MMAs ----
        #pragma unroll
        for (int kb = 0; kb < 2; kb++) {
            uint32_t AH[4], AL[4], bh[16], bl[16];
            *(uint4*)AH = *(const uint4*)&AF[AFI(0,kb,warp,lane,0)];
            *(uint4*)AL = *(const uint4*)&AF[AFI(1,kb,warp,lane,0)];
            #pragma unroll
            for (int q = 0; q < 4; q++) {
                *(uint4*)&bh[q*4] = *(const uint4*)&BF[BFI(0,kb,lane,q*4)];
                *(uint4*)&bl[q*4] = *(const uint4*)&BF[BFI(1,kb,lane,q*4)];
            }
            #pragma unroll
            for (int nt = 0; nt < 8; nt++) {
                mma16(acc[nt], AH, bh[nt*2], bh[nt*2+1]);
                mma16(acc[nt], AH, bl[nt*2], bl[nt*2+1]);
                mma16(acc[nt], AL, bh[nt*2], bh[nt*2+1]);
            }
        }
        __syncthreads();
    }

    // epilogue
    const int g = lane >> 2, t = lane & 3;
    #pragma unroll
    for (int nt = 0; nt < 8; nt++) {
        const int n = nt*8 + 2*t;
        const float b0 = bias[n], b1 = bias[n+1];
        const int m_a = m0 + warp*16 + g, m_b = m_a + 8;
        {
            const int bb_ = m_a >> 11, s = m_a & (SS-1);
            *(float2*)&outp[(((size_t)bb_*HH + h)*SS + s)*DHD + n] =
                make_float2(acc[nt][0] + b0, acc[nt][1] + b1);
        }
        {
            const int bb_ = m_b >> 11, s = m_b & (SS-1);
            *(float2*)&outp[(((size_t)bb_*HH + h)*SS + s)*DHD + n] =
                make_float2(acc[nt][2] + b0, acc[nt][3] + b1);
        }
    }
}

// ---------------------------------------------------------------------------
// Kernel 2: flash attention, bf16 3-split. Q-tile 128 rows, KV-tile 64 keys.
// P re-fragmented lane-locally (m16n8k16 C-frag == A-frag positions).
// grid (16, 16, 2), 256 thr, dyn smem 73728 B
// ---------------------------------------------------------------------------
#define QFI(s,kb,wb,l,r) (((((s)*4+(kb))*8+(wb))*32+(l))*4+(r))   // 8192 words
#define KFI(s,kb,l,i)    ((((s)*4+(kb))*32+(l))*20+(i))           // 5120 words
#define ATT_SMEM_BYTES ((8192 + 5120 + 5120) * 4)

__global__ __launch_bounds__(256) void attn_kernel()
{
    extern __shared__ uint32_t sm[];
    uint32_t* QF = sm;            // [2][4][8][32][4]
    uint32_t* KF = sm + 8192;     // [2][4][32][20]
    uint32_t* VF = sm + 13312;    // [2][4][32][20]

    const int tid  = threadIdx.x;
    const int lane = tid & 31, warp = tid >> 5;
    const int g = lane >> 2, t = lane & 3;
    const int qbase = blockIdx.x * 128;
    const int h = blockIdx.y, b = blockIdx.z;
    const size_t head_base = ((size_t)b * HH + h) * SS;

    // ---- stage Q once (pre-scaled), fragment order ----
    {
        const int r = tid >> 1, dseg = (tid & 1) * 32;
        const int wb = r >> 4, gg = r & 7, rh = (r >> 3) & 1;
        const float* qr = &g_q[(head_base + qbase + r) * DHD + dseg];
        #pragma unroll
        for (int c4 = 0; c4 < 8; c4++) {
            const int d0 = dseg + c4*4;
            const int kb = d0 >> 4, cc = d0 & 15;
            const int reg = rh + 2*(cc >> 3), t0 = (cc & 7) >> 1, ln = gg*4 + t0;
            const float4 v = *(const float4*)&qr[c4*4];
            uint32_t h0,l0,h1,l1;
            split_pair(v.x*0.125f, v.y*0.125f, h0, l0);
            split_pair(v.z*0.125f, v.w*0.125f, h1, l1);
            QF[QFI(0,kb,wb,ln,  reg)] = h0;
            QF[QFI(0,kb,wb,ln+1,reg)] = h1;
            QF[QFI(1,kb,wb,ln,  reg)] = l0;
            QF[QFI(1,kb,wb,ln+1,reg)] = l1;
        }
    }

    float O[8][4] = {};
    float mx0 = -1e30f, mx1 = -1e30f, l0s = 0.f, l1s = 0.f;

    // staging roles for K/V
    const int key = tid >> 2, dsegK = (tid & 3) * 16, kbK = tid & 3;
    const int gK = key & 7, ntK = key >> 3;
    const int kpV = tid >> 3, d8 = (tid & 7) * 8;
    const int kbV = kpV >> 3, regV = (kpV >> 2) & 1, tV = kpV & 3;

    for (int kt = 0; kt < SS; kt += 64) {
        // ---- stage K (frag B layout) ----
        {
            const float* kr = &g_k[(head_base + kt + key) * DHD + dsegK];
            #pragma unroll
            for (int c4 = 0; c4 < 4; c4++) {
                const int cc = c4*4;
                const int reg = cc >> 3, t0 = (cc & 7) >> 1;
                const float4 v = *(const float4*)&kr[c4*4];
                uint32_t h0,l0,h1,l1;
                split_pair(v.x, v.y, h0, l0);
                split_pair(v.z, v.w, h1, l1);
                KF[KFI(0,kbK,gK*4+t0,  ntK*2+reg)] = h0;
                KF[KFI(0,kbK,gK*4+t0+1,ntK*2+reg)] = h1;
                KF[KFI(1,kbK,gK*4+t0,  ntK*2+reg)] = l0;
                KF[KFI(1,kbK,gK*4+t0+1,ntK*2+reg)] = l1;
            }
        }
        // ---- stage V (frag B layout; pack along key pairs) ----
        {
            const float* v0r = &g_v[(head_base + kt + 2*kpV    ) * DHD + d8];
            const float* v1r = &g_v[(head_base + kt + 2*kpV + 1) * DHD + d8];
            float ve[8], vo[8];
            *(float4*)&ve[0] = *(const float4*)&v0r[0];
            *(float4*)&ve[4] = *(const float4*)&v0r[4];
            *(float4*)&vo[0] = *(const float4*)&v1r[0];
            *(float4*)&vo[4] = *(const float4*)&v1r[4];
            #pragma unroll
            for (int j = 0; j < 8; j++) {
                const int d = d8 + j, gn = d & 7, nt = d >> 3;
                uint32_t hh, ll;
                split_pair(ve[j], vo[j], hh, ll);
                VF[KFI(0,kbV,gn*4+tV,nt*2+regV)] = hh;
                VF[KFI(1,kbV,gn*4+tV,nt*2+regV)] = ll;
            }
        }
        __syncthreads();

        // ---- S = (Q/8) @ K^T ----
        float S[8][4] = {};
        #pragma unroll
        for (int kb = 0; kb < 4; kb++) {
            uint32_t QH[4], QL[4], kh[16], kl[16];
            *(uint4*)QH = *(const uint4*)&QF[QFI(0,kb,warp,lane,0)];
            *(uint4*)QL = *(const uint4*)&QF[QFI(1,kb,warp,lane,0)];
            #pragma unroll
            for (int q = 0; q < 4; q++) {
                *(uint4*)&kh[q*4] = *(const uint4*)&KF[KFI(0,kb,lane,q*4)];
                *(uint4*)&kl[q*4] = *(const uint4*)&KF[KFI(1,kb,lane,q*4)];
            }
            #pragma unroll
            for (int nt = 0; nt < 8; nt++) {
                mma16(S[nt], QH, kh[nt*2], kh[nt*2+1]);
                mma16(S[nt], QH, kl[nt*2], kl[nt*2+1]);
                mma16(S[nt], QL, kh[nt*2], kh[nt*2+1]);
            }
        }

        // ---- online softmax (row g -> regs 0,1 ; row g+8 -> regs 2,3) ----
        float mt0 = -1e30f, mt1 = -1e30f;
        #pragma unroll
        for (int nt = 0; nt < 8; nt++) {
            mt0 = fmaxf(mt0, fmaxf(S[nt][0], S[nt][1]));
            mt1 = fmaxf(mt1, fmaxf(S[nt][2], S[nt][3]));
        }
        #pragma unroll
        for (int off = 2; off >= 1; off >>= 1) {
            mt0 = fmaxf(mt0, __shfl_xor_sync(0xffffffffu, mt0, off));
            mt1 = fmaxf(mt1, __shfl_xor_sync(0xffffffffu, mt1, off));
        }
        const float mn0 = fmaxf(mx0, mt0), mn1 = fmaxf(mx1, mt1);
        const float c0 = __expf(mx0 - mn0), c1 = __expf(mx1 - mn1);
        float ls0 = 0.f, ls1 = 0.f;
        #pragma unroll
        for (int nt = 0; nt < 8; nt++) {
            S[nt][0] = __expf(S[nt][0] - mn0); ls0 += S[nt][0];
            S[nt][1] = __expf(S[nt][1] - mn0); ls0 += S[nt][1];
            S[nt][2] = __expf(S[nt][2] - mn1); ls1 += S[nt][2];
            S[nt][3] = __expf(S[nt][3] - mn1); ls1 += S[nt][3];
        }
        #pragma unroll
        for (int off = 2; off >= 1; off >>= 1) {
            ls0 += __shfl_xor_sync(0xffffffffu, ls0, off);
            ls1 += __shfl_xor_sync(0xffffffffu, ls1, off);
        }
        l0s = l0s * c0 + ls0;  l1s = l1s * c1 + ls1;
        mx0 = mn0;             mx1 = mn1;
        #pragma unroll
        for (int nt = 0; nt < 8; nt++) {
            O[nt][0] *= c0; O[nt][1] *= c0;
            O[nt][2] *= c1; O[nt][3] *= c1;
        }

        // ---- O += P @ V (P frag is lane-local: C-frag == A-frag positions) ----
        #pragma unroll
        for (int kb = 0; kb < 4; kb++) {
            uint32_t ph[4], pl[4], vh[16], vl[16];
            split_pair(S[2*kb  ][0], S[2*kb  ][1], ph[0], pl[0]);
            split_pair(S[2*kb  ][2], S[2*kb  ][3], ph[1], pl[1]);
            split_pair(S[2*kb+1][0], S[2*kb+1][1], ph[2], pl[2]);
            split_pair(S[2*kb+1][2], S[2*kb+1][3], ph[3], pl[3]);
            #pragma unroll
            for (int q = 0; q < 4; q++) {
                *(uint4*)&vh[q*4] = *(const uint4*)&VF[KFI(0,kb,lane,q*4)];
                *(uint4*)&vl[q*4] = *(const uint4*)&VF[KFI(1,kb,lane,q*4)];
            }
            #pragma unroll
            for (int nt = 0; nt < 8; nt++) {
                mma16(O[nt], ph, vh[nt*2], vh[nt*2+1]);
                mma16(O[nt], ph, vl[nt*2], vl[nt*2+1]);
                mma16(O[nt], pl, vh[nt*2], vh[nt*2+1]);
            }
        }
        __syncthreads();
    }

    // ---- epilogue ----
    const float i0 = 1.f / l0s, i1 = 1.f / l1s;
    #pragma unroll
    for (int nt = 0; nt < 8; nt++) {
        const int n = nt*8 + 2*t;
        const int sa = qbase + warp*16 + g, sb = sa + 8;
        *(float2*)&g_att[((size_t)b*SS + sa)*DD + h*DHD + n] =
            make_float2(O[nt][0]*i0, O[nt][1]*i0);
        *(float2*)&g_att[((size_t)b*SS + sb)*DD + h*DHD + n] =
            make_float2(O[nt][2]*i1, O[nt][3]*i1);
    }
}

// ---------------------------------------------------------------------------
// Kernel 3: output projection. Same skeleton as qkv. grid (32, 16)
// ---------------------------------------------------------------------------
__global__ __launch_bounds__(256) void out_kernel(
    const float* __restrict__ Wo, const float* __restrict__ bo, float* __restrict__ out)
{
    __shared__ uint32_t AF[2*2*8*32*4];
    __shared__ uint32_t BF[2*2*32*20];

    const int tid  = threadIdx.x;
    const int lane = tid & 31, warp = tid >> 5;
    const int m0 = blockIdx.x * 128;
    const int n0 = blockIdx.y * 64;

    float acc[8][4] = {};

    const int ar = tid >> 1, akb = tid & 1;
    const int awb = ar >> 4, ag = ar & 7, arh = (ar >> 3) & 1;
    const int kp = tid >> 4, n4 = (tid & 15) * 4;
    const int kbB = kp >> 3, regB = (kp >> 2) & 1, tB = kp & 3;

    float4 pa[4]; float4 pb0, pb1;
    {
        const float* xr = &g_att[(size_t)(m0 + ar) * DD + akb*16];
        #pragma unroll
        for (int c = 0; c < 4; c++) pa[c] = *(const float4*)&xr[c*4];
        pb0 = *(const float4*)&Wo[(size_t)(2*kp  ) * DD + n0 + n4];
        pb1 = *(const float4*)&Wo[(size_t)(2*kp+1) * DD + n0 + n4];
    }

    for (int k0 = 0; k0 < DD; k0 += 32) {
        #pragma unroll
        for (int c4 = 0; c4 < 4; c4++) {
            const int cc = c4*4, chalf = cc >> 3, t0 = (cc & 7) >> 1;
            const int reg = arh + 2*chalf, ln = ag*4 + t0;
            uint32_t h0,l0,h1,l1;
            split_pair(pa[c4].x, pa[c4].y, h0, l0);
            split_pair(pa[c4].z, pa[c4].w, h1, l1);
            AF[AFI(0,akb,awb,ln,  reg)] = h0;
            AF[AFI(0,akb,awb,ln+1,reg)] = h1;
            AF[AFI(1,akb,awb,ln,  reg)] = l0;
            AF[AFI(1,akb,awb,ln+1,reg)] = l1;
        }
        {
            const float w0[4] = {pb0.x,pb0.y,pb0.z,pb0.w};
            const float w1[4] = {pb1.x,pb1.y,pb1.z,pb1.w};
            #pragma unroll
            for (int j = 0; j < 4; j++) {
                const int n = n4 + j, gn = n & 7, nt = n >> 3;
                uint32_t hh, ll;
                split_pair(w0[j], w1[j], hh, ll);
                BF[BFI(0,kbB,gn*4+tB,nt*2+regB)] = hh;
                BF[BFI(1,kbB,gn*4+tB,nt*2+regB)] = ll;
            }
        }
        __syncthreads();
        if (k0 + 32 < DD) {
            const float* xr = &g_att[(size_t)(m0 + ar) * DD + k0 + 32 + akb*16];
            #pragma unroll
            for (int c = 0; c < 4; c++) pa[c] = *(const float4*)&xr[c*4];
            pb0 = *(const float4*)&Wo[(size_t)(k0+32 + 2*kp  ) * DD + n0 + n4];
            pb1 = *(const float4*)&Wo[(size_t)(k0+32 + 2*kp+1) * DD + n0 + n4];
        }
        #pragma unroll
        for (int kb = 0; kb < 2; kb++) {
            uint32_t AH[4], AL[4], bh[16], bl[16];
            *(uint4*)AH = *(const uint4*)&AF[AFI(0,kb,warp,lane,0)];
            *(uint4*)AL = *(const uint4*)&AF[AFI(1,kb,warp,lane,0)];
            #pragma unroll
            for (int q = 0; q < 4; q++) {
                *(uint4*)&bh[q*4] = *(const uint4*)&BF[BFI(0,kb,lane,q*4)];
                *(uint4*)&bl[q*4] = *(const uint4*)&BF[BFI(1,kb,lane,q*4)];
            }
            #pragma unroll
            for (int nt = 0; nt < 8; nt++) {
                mma16(acc[nt], AH, bh[nt*2], bh[nt*2+1]);
                mma16(acc[nt], AH, bl[nt*2], bl[nt*2+1]);
                mma16(acc[nt], AL, bh[nt*2], bh[nt*2+1]);
            }
        }
        __syncthreads();
    }

    const int g = lane >> 2, t = lane & 3;
    #pragma unroll
    for (int nt = 0; nt < 8; nt++) {
        const int n = n0 + nt*8 + 2*t;
        const float b0 = bo[n], b1 = bo[n+1];
        const int m_a = m0 + warp*16 + g, m_b = m_a + 8;
        *(float2*)&out[(size_t)m_a * DD + n] = make_float2(acc[nt][0] + b0, acc[nt][1] + b1);
        *(float2*)&out[(size_t)m_b * DD + n] = make_float2(acc[nt][2] + b0, acc[nt][3] + b1);
    }
}

// ---------------------------------------------------------------------------
extern "C" void kernel_launch(void* const* d_in, const int* in_sizes, int n_in,
                              void* d_out, int out_size)
{
    (void)in_sizes; (void)n_in; (void)out_size;
    const float* x  = (const float*)d_in[0];
    const float* Wq = (const float*)d_in[1];
    const float* Wk = (const float*)d_in[2];
    const float* Wv = (const float*)d_in[3];
    const float* bq = (const float*)d_in[4];
    const float* bk = (const float*)d_in[5];
    const float* bv = (const float*)d_in[6];
    const float* Wo = (const float*)d_in[7];
    const float* bo = (const float*)d_in[8];
    float* out = (float*)d_out;

    (void)cudaFuncSetAttribute(attn_kernel, cudaFuncAttributeMaxDynamicSharedMemorySize,
                               ATT_SMEM_BYTES);

    qkv_kernel<<<dim3(MM/128, 3*HH), 256>>>(x, Wq, Wk, Wv, bq, bk, bv);
    attn_kernel<<<dim3(SS/128, HH, BB), 256, ATT_SMEM_BYTES>>>();
    out_kernel<<<dim3(MM/128, DD/64), 256>>>(Wo, bo, out);
}

// round 8
// speedup vs baseline: 1.8762x; 1.1669x over previous
#include <cuda_runtime.h>
#include <cuda_bf16.h>
#include <stdint.h>

#define BB 2
#define SS 2048
#define DD 1024
#define HH 16
#define DHD 64
#define MM (BB*SS)      // 4096
#define NHEAD (BB*HH)   // 32

typedef __nv_bfloat16 bf16;

// ---------------------------------------------------------------------------
// Globals: 6 bf16 planes (48MB) + float att (16MB) = 64MB, same total as the
// passing rounds 2-5. No other new ingredient classes vs round 5.
// ---------------------------------------------------------------------------
#define DEVARR __device__ __align__(16)
DEVARR bf16 QHg[(size_t)NHEAD*SS*DHD]; DEVARR bf16 QLg[(size_t)NHEAD*SS*DHD];
DEVARR bf16 KHg[(size_t)NHEAD*SS*DHD]; DEVARR bf16 KLg[(size_t)NHEAD*SS*DHD];
DEVARR bf16 VHg[(size_t)NHEAD*SS*DHD]; DEVARR bf16 VLg[(size_t)NHEAD*SS*DHD];
__device__ float g_att[(size_t)MM*DD];

// ---------------------------------------------------------------------------
__device__ __forceinline__ void split_pair(float x0, float x1, uint32_t& hi, uint32_t& lo) {
    __nv_bfloat16 h0 = __float2bfloat16_rn(x0);
    __nv_bfloat16 h1 = __float2bfloat16_rn(x1);
    __nv_bfloat16 l0 = __float2bfloat16_rn(x0 - __bfloat162float(h0));
    __nv_bfloat16 l1 = __float2bfloat16_rn(x1 - __bfloat162float(h1));
    hi = ((uint32_t)__bfloat16_as_ushort(h1) << 16) | (uint32_t)__bfloat16_as_ushort(h0);
    lo = ((uint32_t)__bfloat16_as_ushort(l1) << 16) | (uint32_t)__bfloat16_as_ushort(l0);
}
__device__ __forceinline__ void mma16(float* d, const uint32_t* a, uint32_t b0, uint32_t b1) {
    asm volatile("mma.sync.aligned.m16n8k16.row.col.f32.bf16.bf16.f32 "
        "{%0,%1,%2,%3}, {%4,%5,%6,%7}, {%8,%9}, {%0,%1,%2,%3};"
        : "+f"(d[0]), "+f"(d[1]), "+f"(d[2]), "+f"(d[3])
        : "r"(a[0]), "r"(a[1]), "r"(a[2]), "r"(a[3]), "r"(b0), "r"(b1));
}

// Fragment-order smem indices (identical to the round-5 proven layout)
#define AFI(s,kb,wb,l,r) (((((s)*2+(kb))*8+(wb))*32+(l))*4+(r))
#define BFI(s,kb,l,i)    ((((s)*2+(kb))*32+(l))*20+(i))

// ---------------------------------------------------------------------------
// Kernel 1: fused QKV projection, TWO heads per block (BN=128).
// grid (32, 24): y -> which=y/8, head pair (2*(y%8), 2*(y%8)+1). 256 thr.
// Epilogue writes pre-split bf16 planes (q pre-scaled by 0.125).
// ---------------------------------------------------------------------------
__global__ __launch_bounds__(256) void qkv_kernel(
    const float* __restrict__ x,
    const float* __restrict__ Wq, const float* __restrict__ Wk, const float* __restrict__ Wv,
    const float* __restrict__ bq, const float* __restrict__ bk, const float* __restrict__ bv)
{
    __shared__ uint32_t AF[2*2*8*32*4];      // 16 KB
    __shared__ uint32_t BF[2][2*2*32*20];    // 2 x 10 KB (one per head)

    const int tid  = threadIdx.x;
    const int lane = tid & 31, warp = tid >> 5;
    const int m0 = blockIdx.x * 128;
    const int which = blockIdx.y >> 3, hp = blockIdx.y & 7;
    const int h0 = 2*hp, h1 = 2*hp + 1;

    const float* Wb = (which == 0) ? Wq : (which == 1) ? Wk : Wv;
    const float* W0 = Wb + (size_t)h0 * DD * DHD;
    const float* W1 = Wb + (size_t)h1 * DD * DHD;

    float acc[16][4] = {};

    const int ar = tid >> 1, akb = tid & 1;
    const int awb = ar >> 4, ag = ar & 7, arh = (ar >> 3) & 1;
    const int kp = tid >> 4, n4 = (tid & 15) * 4;
    const int kbB = kp >> 3, regB = (kp >> 2) & 1, tB = kp & 3;

    float4 pa[4]; float4 p00, p01, p10, p11;
    {
        const float* xr = &x[(size_t)(m0 + ar) * DD + akb*16];
        #pragma unroll
        for (int c = 0; c < 4; c++) pa[c] = *(const float4*)&xr[c*4];
        p00 = *(const float4*)&W0[(size_t)(2*kp  ) * DHD + n4];
        p01 = *(const float4*)&W0[(size_t)(2*kp+1) * DHD + n4];
        p10 = *(const float4*)&W1[(size_t)(2*kp  ) * DHD + n4];
        p11 = *(const float4*)&W1[(size_t)(2*kp+1) * DHD + n4];
    }

    for (int k0 = 0; k0 < DD; k0 += 32) {
        // ---- split + store A ----
        #pragma unroll
        for (int c4 = 0; c4 < 4; c4++) {
            const int cc = c4*4, chalf = cc >> 3, t0 = (cc & 7) >> 1;
            const int reg = arh + 2*chalf, ln = ag*4 + t0;
            uint32_t h0w,l0w,h1w,l1w;
            split_pair(pa[c4].x, pa[c4].y, h0w, l0w);
            split_pair(pa[c4].z, pa[c4].w, h1w, l1w);
            AF[AFI(0,akb,awb,ln,  reg)] = h0w;
            AF[AFI(0,akb,awb,ln+1,reg)] = h1w;
            AF[AFI(1,akb,awb,ln,  reg)] = l0w;
            AF[AFI(1,akb,awb,ln+1,reg)] = l1w;
        }
        // ---- split + store B (both heads) ----
        #pragma unroll
        for (int hs = 0; hs < 2; hs++) {
            const float4 a = hs ? p10 : p00;
            const float4 b = hs ? p11 : p01;
            const float w0[4] = {a.x,a.y,a.z,a.w};
            const float w1[4] = {b.x,b.y,b.z,b.w};
            #pragma unroll
            for (int j = 0; j < 4; j++) {
                const int n = n4 + j, gn = n & 7, nt = n >> 3;
                uint32_t hh, ll;
                split_pair(w0[j], w1[j], hh, ll);
                BF[hs][BFI(0,kbB,gn*4+tB,nt*2+regB)] = hh;
                BF[hs][BFI(1,kbB,gn*4+tB,nt*2+regB)] = ll;
            }
        }
        __syncthreads();
        if (k0 + 32 < DD) {   // prefetch next chunk (overlaps MMAs)
            const float* xr = &x[(size_t)(m0 + ar) * DD + k0 + 32 + akb*16];
            #pragma unroll
            for (int c = 0; c < 4; c++) pa[c] = *(const float4*)&xr[c*4];
            p00 = *(const float4*)&W0[(size_t)(k0+32 + 2*kp  ) * DHD + n4];
            p01 = *(const float4*)&W0[(size_t)(k0+32 + 2*kp+1) * DHD + n4];
            p10 = *(const float4*)&W1[(size_t)(k0+32 + 2*kp  ) * DHD + n4];
            p11 = *(const float4*)&W1[(size_t)(k0+32 + 2*kp+1) * DHD + n4];
        }
        #pragma unroll
        for (int kb = 0; kb < 2; kb++) {
            uint32_t AH[4], AL[4];
            *(uint4*)AH = *(const uint4*)&AF[AFI(0,kb,warp,lane,0)];
            *(uint4*)AL = *(const uint4*)&AF[AFI(1,kb,warp,lane,0)];
            #pragma unroll
            for (int hs = 0; hs < 2; hs++) {
                uint32_t bh[16], bl[16];
                #pragma unroll
                for (int q = 0; q < 4; q++) {
                    *(uint4*)&bh[q*4] = *(const uint4*)&BF[hs][BFI(0,kb,lane,q*4)];
                    *(uint4*)&bl[q*4] = *(const uint4*)&BF[hs][BFI(1,kb,lane,q*4)];
                }
                #pragma unroll
                for (int nt = 0; nt < 8; nt++) {
                    float* ac = acc[hs*8 + nt];
                    mma16(ac, AH, bh[nt*2], bh[nt*2+1]);
                    mma16(ac, AH, bl[nt*2], bl[nt*2+1]);
                    mma16(ac, AL, bh[nt*2], bh[nt*2+1]);
                }
            }
        }
        __syncthreads();
    }

    // ---- epilogue: bias, scale(q), split, store planes ----
    const float* biasb = (which == 0) ? bq : (which == 1) ? bk : bv;
    bf16* oh = (which == 0) ? QHg : (which == 1) ? KHg : VHg;
    bf16* ol = (which == 0) ? QLg : (which == 1) ? KLg : VLg;
    const float sc = (which == 0) ? 0.125f : 1.0f;

    const int g = lane >> 2, t4 = lane & 3;
    #pragma unroll
    for (int idx = 0; idx < 16; idx++) {
        const int head = (idx < 8) ? h0 : h1;
        const int n64 = (idx & 7)*8 + 2*t4;
        const float b0 = biasb[head*DHD + n64], b1 = biasb[head*DHD + n64 + 1];
        uint32_t hi, lo;
        int m = m0 + warp*16 + g;
        size_t ridx = (((size_t)(m >> 11) * HH + head) * SS + (m & (SS-1))) * DHD + n64;
        split_pair((acc[idx][0] + b0) * sc, (acc[idx][1] + b1) * sc, hi, lo);
        *(uint32_t*)&oh[ridx] = hi; *(uint32_t*)&ol[ridx] = lo;
        m += 8;
        ridx = (((size_t)(m >> 11) * HH + head) * SS + (m & (SS-1))) * DHD + n64;
        split_pair((acc[idx][2] + b0) * sc, (acc[idx][3] + b1) * sc, hi, lo);
        *(uint32_t*)&oh[ridx] = hi; *(uint32_t*)&ol[ridx] = lo;
    }
}

// ---------------------------------------------------------------------------
// Kernel 2: flash attention. Staging is now PURE COPY from pre-split planes
// (K/Q: contiguous u32 pairs; V: byte_perm cross-key repack). Round-5 layout.
// grid (16, 16, 2), 256 thr, dyn smem 73728 B (round-5-proven opt-in size).
// ---------------------------------------------------------------------------
#define QFI(s,kb,wb,l,r) (((((s)*4+(kb))*8+(wb))*32+(l))*4+(r))   // 8192 words
#define KFI(s,kb,l,i)    ((((s)*4+(kb))*32+(l))*20+(i))           // 5120 words
#define ATT_SMEM_BYTES ((8192 + 5120 + 5120) * 4)

__global__ __launch_bounds__(256) void attn_kernel()
{
    extern __shared__ uint32_t sm[];
    uint32_t* QF = sm;
    uint32_t* KF = sm + 8192;
    uint32_t* VF = sm + 13312;

    const int tid  = threadIdx.x;
    const int lane = tid & 31, warp = tid >> 5;
    const int g = lane >> 2, t4 = lane & 3;
    const int q0 = blockIdx.x * 128;
    const int head = blockIdx.z * HH + blockIdx.y;
    const size_t hb = (size_t)head * SS;

    // ---- stage Q once (pure copy; q already biased+scaled+split) ----
    {
        const int r = tid >> 1, dseg = (tid & 1) * 32;
        const int wb = r >> 4, gg = r & 7, rh = (r >> 3) & 1;
        const uint32_t* qhw = (const uint32_t*)(QHg + (hb + q0 + r) * DHD) + dseg/2;
        const uint32_t* qlw = (const uint32_t*)(QLg + (hb + q0 + r) * DHD) + dseg/2;
        uint32_t uh[16], ul[16];
        #pragma unroll
        for (int c = 0; c < 4; c++) {
            *(uint4*)&uh[c*4] = *(const uint4*)&qhw[c*4];
            *(uint4*)&ul[c*4] = *(const uint4*)&qlw[c*4];
        }
        #pragma unroll
        for (int c4 = 0; c4 < 8; c4++) {
            const int d0 = dseg + c4*4;
            const int kb = d0 >> 4, cc = d0 & 15;
            const int reg = rh + 2*(cc >> 3), ln = gg*4 + ((cc & 7) >> 1);
            QF[QFI(0,kb,wb,ln,  reg)] = uh[c4*2];
            QF[QFI(0,kb,wb,ln+1,reg)] = uh[c4*2+1];
            QF[QFI(1,kb,wb,ln,  reg)] = ul[c4*2];
            QF[QFI(1,kb,wb,ln+1,reg)] = ul[c4*2+1];
        }
    }

    float O[8][4] = {};
    float mx0 = -1e30f, mx1 = -1e30f, l0s = 0.f, l1s = 0.f;

    // staging roles
    const int key = tid >> 2, kbK = tid & 3;           // K: one key row, one d-chunk
    const int gK = key & 7, ntK = key >> 3;
    const int kpV = tid >> 3, d8 = (tid & 7) * 8;      // V: key pair, 8 d-values
    const int kbV = kpV >> 3, regV = (kpV >> 2) & 1, tV = kpV & 3, ntV = tid & 7;

    for (int kt = 0; kt < SS; kt += 64) {
        __syncthreads();
        // ---- stage K (pure copy) ----
        {
            const uint32_t* khw = (const uint32_t*)(KHg + (hb + kt + key) * DHD) + kbK*8;
            const uint32_t* klw = (const uint32_t*)(KLg + (hb + kt + key) * DHD) + kbK*8;
            uint32_t uh[8], ul[8];
            *(uint4*)&uh[0] = *(const uint4*)&khw[0];
            *(uint4*)&uh[4] = *(const uint4*)&khw[4];
            *(uint4*)&ul[0] = *(const uint4*)&klw[0];
            *(uint4*)&ul[4] = *(const uint4*)&klw[4];
            #pragma unroll
            for (int c4 = 0; c4 < 4; c4++) {
                const int cc = c4*4;
                const int reg = cc >> 3, t0 = (cc & 7) >> 1;
                KF[KFI(0,kbK,gK*4+t0,  ntK*2+reg)] = uh[c4*2];
                KF[KFI(0,kbK,gK*4+t0+1,ntK*2+reg)] = uh[c4*2+1];
                KF[KFI(1,kbK,gK*4+t0,  ntK*2+reg)] = ul[c4*2];
                KF[KFI(1,kbK,gK*4+t0+1,ntK*2+reg)] = ul[c4*2+1];
            }
        }
        // ---- stage V (byte_perm repack: (key,key+1) pairs along k) ----
        {
            const uint32_t* v0h = (const uint32_t*)(VHg + (hb + kt + 2*kpV    ) * DHD) + d8/2;
            const uint32_t* v1h = (const uint32_t*)(VHg + (hb + kt + 2*kpV + 1) * DHD) + d8/2;
            const uint32_t* v0l = (const uint32_t*)(VLg + (hb + kt + 2*kpV    ) * DHD) + d8/2;
            const uint32_t* v1l = (const uint32_t*)(VLg + (hb + kt + 2*kpV + 1) * DHD) + d8/2;
            uint32_t a0[4], a1[4], b0[4], b1[4];
            *(uint4*)a0 = *(const uint4*)v0h;  *(uint4*)a1 = *(const uint4*)v1h;
            *(uint4*)b0 = *(const uint4*)v0l;  *(uint4*)b1 = *(const uint4*)v1l;
            #pragma unroll
            for (int j = 0; j < 8; j++) {
                const uint32_t sel = (j & 1) ? 0x7632u : 0x5410u;
                VF[KFI(0,kbV, j*4+tV, ntV*2+regV)] = __byte_perm(a0[j>>1], a1[j>>1], sel);
                VF[KFI(1,kbV, j*4+tV, ntV*2+regV)] = __byte_perm(b0[j>>1], b1[j>>1], sel);
            }
        }
        __syncthreads();

        // ---- S = (Q/8) @ K^T ----
        float S[8][4] = {};
        #pragma unroll
        for (int kb = 0; kb < 4; kb++) {
            uint32_t QH[4], QL[4], kh[16], kl[16];
            *(uint4*)QH = *(const uint4*)&QF[QFI(0,kb,warp,lane,0)];
            *(uint4*)QL = *(const uint4*)&QF[QFI(1,kb,warp,lane,0)];
            #pragma unroll
            for (int q = 0; q < 4; q++) {
                *(uint4*)&kh[q*4] = *(const uint4*)&KF[KFI(0,kb,lane,q*4)];
                *(uint4*)&kl[q*4] = *(const uint4*)&KF[KFI(1,kb,lane,q*4)];
            }
            #pragma unroll
            for (int nt = 0; nt < 8; nt++) {
                mma16(S[nt], QH, kh[nt*2], kh[nt*2+1]);
                mma16(S[nt], QH, kl[nt*2], kl[nt*2+1]);
                mma16(S[nt], QL, kh[nt*2], kh[nt*2+1]);
            }
        }

        // ---- online softmax ----
        float mt0 = -1e30f, mt1 = -1e30f;
        #pragma unroll
        for (int nt = 0; nt < 8; nt++) {
            mt0 = fmaxf(mt0, fmaxf(S[nt][0], S[nt][1]));
            mt1 = fmaxf(mt1, fmaxf(S[nt][2], S[nt][3]));
        }
        #pragma unroll
        for (int off = 2; off >= 1; off >>= 1) {
            mt0 = fmaxf(mt0, __shfl_xor_sync(0xffffffffu, mt0, off));
            mt1 = fmaxf(mt1, __shfl_xor_sync(0xffffffffu, mt1, off));
        }
        const float mn0 = fmaxf(mx0, mt0), mn1 = fmaxf(mx1, mt1);
        const float c0 = __expf(mx0 - mn0), c1 = __expf(mx1 - mn1);
        float ls0 = 0.f, ls1 = 0.f;
        #pragma unroll
        for (int nt = 0; nt < 8; nt++) {
            S[nt][0] = __expf(S[nt][0] - mn0); ls0 += S[nt][0];
            S[nt][1] = __expf(S[nt][1] - mn0); ls0 += S[nt][1];
            S[nt][2] = __expf(S[nt][2] - mn1); ls1 += S[nt][2];
            S[nt][3] = __expf(S[nt][3] - mn1); ls1 += S[nt][3];
        }
        #pragma unroll
        for (int off = 2; off >= 1; off >>= 1) {
            ls0 += __shfl_xor_sync(0xffffffffu, ls0, off);
            ls1 += __shfl_xor_sync(0xffffffffu, ls1, off);
        }
        l0s = l0s * c0 + ls0;  l1s = l1s * c1 + ls1;
        mx0 = mn0;             mx1 = mn1;
        #pragma unroll
        for (int nt = 0; nt < 8; nt++) {
            O[nt][0] *= c0; O[nt][1] *= c0;
            O[nt][2] *= c1; O[nt][3] *= c1;
        }

        // ---- O += P @ V (P A-frag lane-local) ----
        #pragma unroll
        for (int kb = 0; kb < 4; kb++) {
            uint32_t ph[4], pl[4], vh[16], vl[16];
            split_pair(S[2*kb  ][0], S[2*kb  ][1], ph[0], pl[0]);
            split_pair(S[2*kb  ][2], S[2*kb  ][3], ph[1], pl[1]);
            split_pair(S[2*kb+1][0], S[2*kb+1][1], ph[2], pl[2]);
            split_pair(S[2*kb+1][2], S[2*kb+1][3], ph[3], pl[3]);
            #pragma unroll
            for (int q = 0; q < 4; q++) {
                *(uint4*)&vh[q*4] = *(const uint4*)&VF[KFI(0,kb,lane,q*4)];
                *(uint4*)&vl[q*4] = *(const uint4*)&VF[KFI(1,kb,lane,q*4)];
            }
            #pragma unroll
            for (int nt = 0; nt < 8; nt++) {
                mma16(O[nt], ph, vh[nt*2], vh[nt*2+1]);
                mma16(O[nt], ph, vl[nt*2], vl[nt*2+1]);
                mma16(O[nt], pl, vh[nt*2], vh[nt*2+1]);
            }
        }
    }

    // ---- epilogue: normalize, write g_att float (concat layout) ----
    const float i0 = 1.f / l0s, i1 = 1.f / l1s;
    #pragma unroll
    for (int nt = 0; nt < 8; nt++) {
        const int n = nt*8 + 2*t4;
        const int sa = q0 + warp*16 + g, sb = sa + 8;
        *(float2*)&g_att[((size_t)blockIdx.z * SS + sa) * DD + blockIdx.y * DHD + n] =
            make_float2(O[nt][0]*i0, O[nt][1]*i0);
        *(float2*)&g_att[((size_t)blockIdx.z * SS + sb) * DD + blockIdx.y * DHD + n] =
            make_float2(O[nt][2]*i1, O[nt][3]*i1);
    }
}

// ---------------------------------------------------------------------------
// Kernel 3: output projection (round-5 verbatim skeleton). grid (32, 16).
// ---------------------------------------------------------------------------
__global__ __launch_bounds__(256) void out_kernel(
    const float* __restrict__ Wo, const float* __restrict__ bo, float* __restrict__ out)
{
    __shared__ uint32_t AF[2*2*8*32*4];
    __shared__ uint32_t BF[2*2*32*20];

    const int tid  = threadIdx.x;
    const int lane = tid & 31, warp = tid >> 5;
    const int m0 = blockIdx.x * 128;
    const int n0 = blockIdx.y * 64;

    float acc[8][4] = {};

    const int ar = tid >> 1, akb = tid & 1;
    const int awb = ar >> 4, ag = ar & 7, arh = (ar >> 3) & 1;
    const int kp = tid >> 4, n4 = (tid & 15) * 4;
    const int kbB = kp >> 3, regB = (kp >> 2) & 1, tB = kp & 3;

    float4 pa[4]; float4 pb0, pb1;
    {
        const float* xr = &g_att[(size_t)(m0 + ar) * DD + akb*16];
        #pragma unroll
        for (int c = 0; c < 4; c++) pa[c] = *(const float4*)&xr[c*4];
        pb0 = *(const float4*)&Wo[(size_t)(2*kp  ) * DD + n0 + n4];
        pb1 = *(const float4*)&Wo[(size_t)(2*kp+1) * DD + n0 + n4];
    }

    for (int k0 = 0; k0 < DD; k0 += 32) {
        #pragma unroll
        for (int c4 = 0; c4 < 4; c4++) {
            const int cc = c4*4, chalf = cc >> 3, t0 = (cc & 7) >> 1;
            const int reg = arh + 2*chalf, ln = ag*4 + t0;
            uint32_t h0w,l0w,h1w,l1w;
            split_pair(pa[c4].x, pa[c4].y, h0w, l0w);
            split_pair(pa[c4].z, pa[c4].w, h1w, l1w);
            AF[AFI(0,akb,awb,ln,  reg)] = h0w;
            AF[AFI(0,akb,awb,ln+1,reg)] = h1w;
            AF[AFI(1,akb,awb,ln,  reg)] = l0w;
            AF[AFI(1,akb,awb,ln+1,reg)] = l1w;
        }
        {
            const float w0[4] = {pb0.x,pb0.y,pb0.z,pb0.w};
            const float w1[4] = {pb1.x,pb1.y,pb1.z,pb1.w};
            #pragma unroll
            for (int j = 0; j < 4; j++) {
                const int n = n4 + j, gn = n & 7, nt = n >> 3;
                uint32_t hh, ll;
                split_pair(w0[j], w1[j], hh, ll);
                BF[BFI(0,kbB,gn*4+tB,nt*2+regB)] = hh;
                BF[BFI(1,kbB,gn*4+tB,nt*2+regB)] = ll;
            }
        }
        __syncthreads();
        if (k0 + 32 < DD) {
            const float* xr = &g_att[(size_t)(m0 + ar) * DD + k0 + 32 + akb*16];
            #pragma unroll
            for (int c = 0; c < 4; c++) pa[c] = *(const float4*)&xr[c*4];
            pb0 = *(const float4*)&Wo[(size_t)(k0+32 + 2*kp  ) * DD + n0 + n4];
            pb1 = *(const float4*)&Wo[(size_t)(k0+32 + 2*kp+1) * DD + n0 + n4];
        }
        #pragma unroll
        for (int kb = 0; kb < 2; kb++) {
            uint32_t AH[4], AL[4], bh[16], bl[16];
            *(uint4*)AH = *(const uint4*)&AF[AFI(0,kb,warp,lane,0)];
            *(uint4*)AL = *(const uint4*)&AF[AFI(1,kb,warp,lane,0)];
            #pragma unroll
            for (int q = 0; q < 4; q++) {
                *(uint4*)&bh[q*4] = *(const uint4*)&BF[BFI(0,kb,lane,q*4)];
                *(uint4*)&bl[q*4] = *(const uint4*)&BF[BFI(1,kb,lane,q*4)];
            }
            #pragma unroll
            for (int nt = 0; nt < 8; nt++) {
                mma16(acc[nt], AH, bh[nt*2], bh[nt*2+1]);
                mma16(acc[nt], AH, bl[nt*2], bl[nt*2+1]);
                mma16(acc[nt], AL, bh[nt*2], bh[nt*2+1]);
            }
        }
        __syncthreads();
    }

    const int g = lane >> 2, t4 = lane & 3;
    #pragma unroll
    for (int nt = 0; nt < 8; nt++) {
        const int n = n0 + nt*8 + 2*t4;
        const float b0 = bo[n], b1 = bo[n+1];
        const int m_a = m0 + warp*16 + g, m_b = m_a + 8;
        *(float2*)&out[(size_t)m_a * DD + n] = make_float2(acc[nt][0] + b0, acc[nt][1] + b1);
        *(float2*)&out[(size_t)m_b * DD + n] = make_float2(acc[nt][2] + b0, acc[nt][3] + b1);
    }
}

// ---------------------------------------------------------------------------
extern "C" void kernel_launch(void* const* d_in, const int* in_sizes, int n_in,
                              void* d_out, int out_size)
{
    (void)in_sizes; (void)n_in; (void)out_size;
    const float* x  = (const float*)d_in[0];
    const float* Wq = (const float*)d_in[1];
    const float* Wk = (const float*)d_in[2];
    const float* Wv = (const float*)d_in[3];
    const float* bq = (const float*)d_in[4];
    const float* bk = (const float*)d_in[5];
    const float* bv = (const float*)d_in[6];
    const float* Wo = (const float*)d_in[7];
    const float* bo = (const float*)d_in[8];
    float* out = (float*)d_out;

    (void)cudaFuncSetAttribute(attn_kernel, cudaFuncAttributeMaxDynamicSharedMemorySize,
                               ATT_SMEM_BYTES);

    qkv_kernel<<<dim3(MM/128, 24), 256>>>(x, Wq, Wk, Wv, bq, bk, bv);
    attn_kernel<<<dim3(SS/128, HH, BB), 256, ATT_SMEM_BYTES>>>();
    out_kernel<<<dim3(MM/128, DD/64), 256>>>(Wo, bo, out);
}

// round 9
// speedup vs baseline: 1.9023x; 1.0139x over previous
#include <cuda_runtime.h>
#include <cuda_bf16.h>
#include <stdint.h>

#define BB 2
#define SS 2048
#define DD 1024
#define HH 16
#define DHD 64
#define MM (BB*SS)      // 4096
#define NHEAD (BB*HH)   // 32

typedef __nv_bfloat16 bf16;

// ---------------------------------------------------------------------------
// Globals: 8 bf16 planes x 8MB = 64MB (the proven-safe total).
// XH/XL hold split(x) for qkv, then are overwritten by attn with split(att).
// ---------------------------------------------------------------------------
#define DEVARR __device__ __align__(16)
DEVARR bf16 XH [(size_t)MM*DD];        DEVARR bf16 XL [(size_t)MM*DD];
DEVARR bf16 QHg[(size_t)NHEAD*SS*DHD]; DEVARR bf16 QLg[(size_t)NHEAD*SS*DHD];
DEVARR bf16 KHg[(size_t)NHEAD*SS*DHD]; DEVARR bf16 KLg[(size_t)NHEAD*SS*DHD];
DEVARR bf16 VHg[(size_t)NHEAD*SS*DHD]; DEVARR bf16 VLg[(size_t)NHEAD*SS*DHD];

// ---------------------------------------------------------------------------
__device__ __forceinline__ void split_pair(float x0, float x1, uint32_t& hi, uint32_t& lo) {
    __nv_bfloat16 h0 = __float2bfloat16_rn(x0);
    __nv_bfloat16 h1 = __float2bfloat16_rn(x1);
    __nv_bfloat16 l0 = __float2bfloat16_rn(x0 - __bfloat162float(h0));
    __nv_bfloat16 l1 = __float2bfloat16_rn(x1 - __bfloat162float(h1));
    hi = ((uint32_t)__bfloat16_as_ushort(h1) << 16) | (uint32_t)__bfloat16_as_ushort(h0);
    lo = ((uint32_t)__bfloat16_as_ushort(l1) << 16) | (uint32_t)__bfloat16_as_ushort(l0);
}
__device__ __forceinline__ void mma16(float* d, const uint32_t* a, uint32_t b0, uint32_t b1) {
    asm volatile("mma.sync.aligned.m16n8k16.row.col.f32.bf16.bf16.f32 "
        "{%0,%1,%2,%3}, {%4,%5,%6,%7}, {%8,%9}, {%0,%1,%2,%3};"
        : "+f"(d[0]), "+f"(d[1]), "+f"(d[2]), "+f"(d[3])
        : "r"(a[0]), "r"(a[1]), "r"(a[2]), "r"(a[3]), "r"(b0), "r"(b1));
}

// Fragment-order indices (round-5/8 proven layout), within one buffer
#define AFI(s,kb,wb,l,r) (((((s)*2+(kb))*8+(wb))*32+(l))*4+(r))   // 4096 words
#define BFI(s,kb,l,i)    ((((s)*2+(kb))*32+(l))*20+(i))           // 2560 words

// ---------------------------------------------------------------------------
// prep: split x into hi/lo planes (one time)
// ---------------------------------------------------------------------------
__global__ __launch_bounds__(256) void splitx_kernel(const float* __restrict__ src) {
    const size_t i = ((size_t)blockIdx.x * 256 + threadIdx.x) * 4;
    const float4 v = *(const float4*)&src[i];
    uint32_t h0, l0, h1, l1;
    split_pair(v.x, v.y, h0, l0);
    split_pair(v.z, v.w, h1, l1);
    *(uint2*)&XH[i] = make_uint2(h0, h1);
    *(uint2*)&XL[i] = make_uint2(l0, l1);
}

// ---------------------------------------------------------------------------
// shared staging helpers (A = pre-split planes, pure copy; B = fp32, split)
// ---------------------------------------------------------------------------
__device__ __forceinline__ void storeA(uint32_t* sm, int base,
    const uint4* pah, const uint4* pal, int akb, int awb, int ag, int arh)
{
    uint32_t uh[8], ul[8];
    *(uint4*)&uh[0] = pah[0];  *(uint4*)&uh[4] = pah[1];
    *(uint4*)&ul[0] = pal[0];  *(uint4*)&ul[4] = pal[1];
    #pragma unroll
    for (int c4 = 0; c4 < 4; c4++) {
        const int cc = c4*4, chalf = cc >> 3, t0 = (cc & 7) >> 1;
        const int reg = arh + 2*chalf, ln = ag*4 + t0;
        sm[base + AFI(0,akb,awb,ln,  reg)] = uh[2*c4];
        sm[base + AFI(0,akb,awb,ln+1,reg)] = uh[2*c4+1];
        sm[base + AFI(1,akb,awb,ln,  reg)] = ul[2*c4];
        sm[base + AFI(1,akb,awb,ln+1,reg)] = ul[2*c4+1];
    }
}
__device__ __forceinline__ void storeB(uint32_t* sm, int base,
    float4 pb0, float4 pb1, int n4, int kbB, int regB, int tB)
{
    const float w0[4] = {pb0.x,pb0.y,pb0.z,pb0.w};
    const float w1[4] = {pb1.x,pb1.y,pb1.z,pb1.w};
    #pragma unroll
    for (int j = 0; j < 4; j++) {
        const int n = n4 + j, gn = n & 7, nt = n >> 3;
        uint32_t hh, ll;
        split_pair(w0[j], w1[j], hh, ll);
        sm[base + BFI(0,kbB,gn*4+tB,nt*2+regB)] = hh;
        sm[base + BFI(1,kbB,gn*4+tB,nt*2+regB)] = ll;
    }
}

// ---------------------------------------------------------------------------
// Kernel 1: fused QKV projection. 2 heads/block. grid (32, 24), 256 thr.
// Double-buffered smem (73728 B), ONE sync per iter.
// ---------------------------------------------------------------------------
#define QAF(buf)     ((buf)*4096)
#define QBF(buf,hs)  (8192 + (buf)*5120 + (hs)*2560)
#define QKV_SMEM (18432*4)   // 73728

__global__ __launch_bounds__(256) void qkv_kernel(
    const float* __restrict__ Wq, const float* __restrict__ Wk, const float* __restrict__ Wv,
    const float* __restrict__ bq, const float* __restrict__ bk, const float* __restrict__ bv)
{
    extern __shared__ uint32_t sm[];
    const int tid  = threadIdx.x;
    const int lane = tid & 31, warp = tid >> 5;
    const int m0 = blockIdx.x * 128;
    const int which = blockIdx.y >> 3, hp = blockIdx.y & 7;
    const int h0 = 2*hp, h1 = 2*hp + 1;

    const float* Wb = (which == 0) ? Wq : (which == 1) ? Wk : Wv;
    const float* W0 = Wb + (size_t)h0 * DD * DHD;
    const float* W1 = Wb + (size_t)h1 * DD * DHD;

    float acc[16][4] = {};

    const int ar = tid >> 1, akb = tid & 1;
    const int awb = ar >> 4, ag = ar & 7, arh = (ar >> 3) & 1;
    const int kp = tid >> 4, n4 = (tid & 15) * 4;
    const int kbB = kp >> 3, regB = (kp >> 2) & 1, tB = kp & 3;

    const uint32_t* xh = (const uint32_t*)(XH + (size_t)(m0 + ar) * DD) + akb*8;
    const uint32_t* xl = (const uint32_t*)(XL + (size_t)(m0 + ar) * DD) + akb*8;

    uint4 pah[2], pal[2];
    float4 p00, p01, p10, p11;

    // chunk 0 -> regs -> buf0
    pah[0] = *(const uint4*)&xh[0];  pah[1] = *(const uint4*)&xh[4];
    pal[0] = *(const uint4*)&xl[0];  pal[1] = *(const uint4*)&xl[4];
    p00 = *(const float4*)&W0[(size_t)(2*kp  ) * DHD + n4];
    p01 = *(const float4*)&W0[(size_t)(2*kp+1) * DHD + n4];
    p10 = *(const float4*)&W1[(size_t)(2*kp  ) * DHD + n4];
    p11 = *(const float4*)&W1[(size_t)(2*kp+1) * DHD + n4];
    storeA(sm, QAF(0), pah, pal, akb, awb, ag, arh);
    storeB(sm, QBF(0,0), p00, p01, n4, kbB, regB, tB);
    storeB(sm, QBF(0,1), p10, p11, n4, kbB, regB, tB);
    // chunk 1 -> regs
    pah[0] = *(const uint4*)&xh[16];  pah[1] = *(const uint4*)&xh[20];
    pal[0] = *(const uint4*)&xl[16];  pal[1] = *(const uint4*)&xl[20];
    p00 = *(const float4*)&W0[(size_t)(32 + 2*kp  ) * DHD + n4];
    p01 = *(const float4*)&W0[(size_t)(32 + 2*kp+1) * DHD + n4];
    p10 = *(const float4*)&W1[(size_t)(32 + 2*kp  ) * DHD + n4];
    p11 = *(const float4*)&W1[(size_t)(32 + 2*kp+1) * DHD + n4];
    __syncthreads();

    for (int it = 0; it < 32; it++) {
        const int buf = it & 1;
        if (it + 1 < 32) {   // stage chunk it+1 into other buffer (overlaps MMAs)
            storeA(sm, QAF(buf^1), pah, pal, akb, awb, ag, arh);
            storeB(sm, QBF(buf^1,0), p00, p01, n4, kbB, regB, tB);
            storeB(sm, QBF(buf^1,1), p10, p11, n4, kbB, regB, tB);
        }
        if (it + 2 < 32) {   // prefetch chunk it+2
            const int w = (it+2)*16;
            pah[0] = *(const uint4*)&xh[w];  pah[1] = *(const uint4*)&xh[w+4];
            pal[0] = *(const uint4*)&xl[w];  pal[1] = *(const uint4*)&xl[w+4];
            const size_t kr = (size_t)(it+2)*32 + 2*kp;
            p00 = *(const float4*)&W0[kr*DHD + n4];
            p01 = *(const float4*)&W0[(kr+1)*DHD + n4];
            p10 = *(const float4*)&W1[kr*DHD + n4];
            p11 = *(const float4*)&W1[(kr+1)*DHD + n4];
        }
        #pragma unroll
        for (int kb = 0; kb < 2; kb++) {
            uint32_t AH[4], AL[4];
            *(uint4*)AH = *(const uint4*)&sm[QAF(buf) + AFI(0,kb,warp,lane,0)];
            *(uint4*)AL = *(const uint4*)&sm[QAF(buf) + AFI(1,kb,warp,lane,0)];
            #pragma unroll
            for (int hs = 0; hs < 2; hs++) {
                uint32_t bh[16], bl[16];
                #pragma unroll
                for (int q = 0; q < 4; q++) {
                    *(uint4*)&bh[q*4] = *(const uint4*)&sm[QBF(buf,hs) + BFI(0,kb,lane,q*4)];
                    *(uint4*)&bl[q*4] = *(const uint4*)&sm[QBF(buf,hs) + BFI(1,kb,lane,q*4)];
                }
                #pragma unroll
                for (int nt = 0; nt < 8; nt++) {
                    float* ac = acc[hs*8 + nt];
                    mma16(ac, AH, bh[nt*2], bh[nt*2+1]);
                    mma16(ac, AH, bl[nt*2], bl[nt*2+1]);
                    mma16(ac, AL, bh[nt*2], bh[nt*2+1]);
                }
            }
        }
        __syncthreads();
    }

    // epilogue (round-8 verbatim): bias, scale(q), split, store planes
    const float* biasb = (which == 0) ? bq : (which == 1) ? bk : bv;
    bf16* oh = (which == 0) ? QHg : (which == 1) ? KHg : VHg;
    bf16* ol = (which == 0) ? QLg : (which == 1) ? KLg : VLg;
    const float sc = (which == 0) ? 0.125f : 1.0f;

    const int g = lane >> 2, t4 = lane & 3;
    #pragma unroll
    for (int idx = 0; idx < 16; idx++) {
        const int head = (idx < 8) ? h0 : h1;
        const int n64 = (idx & 7)*8 + 2*t4;
        const float b0 = biasb[head*DHD + n64], b1 = biasb[head*DHD + n64 + 1];
        uint32_t hi, lo;
        int m = m0 + warp*16 + g;
        size_t ridx = (((size_t)(m >> 11) * HH + head) * SS + (m & (SS-1))) * DHD + n64;
        split_pair((acc[idx][0] + b0) * sc, (acc[idx][1] + b1) * sc, hi, lo);
        *(uint32_t*)&oh[ridx] = hi; *(uint32_t*)&ol[ridx] = lo;
        m += 8;
        ridx = (((size_t)(m >> 11) * HH + head) * SS + (m & (SS-1))) * DHD + n64;
        split_pair((acc[idx][2] + b0) * sc, (acc[idx][3] + b1) * sc, hi, lo);
        *(uint32_t*)&oh[ridx] = hi; *(uint32_t*)&ol[ridx] = lo;
    }
}

// ---------------------------------------------------------------------------
// Kernel 2: flash attention. Round-8 structure, but K/V for the NEXT tile are
// prefetched into registers BEFORE the compute phase (hides gmem latency).
// grid (16, 16, 2), 256 thr, dyn smem 73728 B.
// ---------------------------------------------------------------------------
#define QFI(s,kb,wb,l,r) (((((s)*4+(kb))*8+(wb))*32+(l))*4+(r))   // 8192 words
#define KFI(s,kb,l,i)    ((((s)*4+(kb))*32+(l))*20+(i))           // 5120 words
#define ATT_SMEM_BYTES ((8192 + 5120 + 5120) * 4)

__global__ __launch_bounds__(256) void attn_kernel()
{
    extern __shared__ uint32_t sm[];
    uint32_t* QF = sm;
    uint32_t* KF = sm + 8192;
    uint32_t* VF = sm + 13312;

    const int tid  = threadIdx.x;
    const int lane = tid & 31, warp = tid >> 5;
    const int g = lane >> 2, t4 = lane & 3;
    const int q0 = blockIdx.x * 128;
    const int head = blockIdx.z * HH + blockIdx.y;
    const size_t hb = (size_t)head * SS;

    // staging roles
    const int key = tid >> 2, kbK = tid & 3;
    const int gK = key & 7, ntK = key >> 3;
    const int kpV = tid >> 3, d8 = (tid & 7) * 8;
    const int kbV = kpV >> 3, regV = (kpV >> 2) & 1, tV = kpV & 3, ntV = tid & 7;

    const uint32_t* khw = (const uint32_t*)(KHg + (hb + key) * DHD) + kbK*8;
    const uint32_t* klw = (const uint32_t*)(KLg + (hb + key) * DHD) + kbK*8;
    const uint32_t* v0h = (const uint32_t*)(VHg + (hb + 2*kpV    ) * DHD) + d8/2;
    const uint32_t* v1h = (const uint32_t*)(VHg + (hb + 2*kpV + 1) * DHD) + d8/2;
    const uint32_t* v0l = (const uint32_t*)(VLg + (hb + 2*kpV    ) * DHD) + d8/2;
    const uint32_t* v1l = (const uint32_t*)(VLg + (hb + 2*kpV + 1) * DHD) + d8/2;
    const size_t krow = (size_t)64 * DHD / 2;   // u32 words per 64-key tile step

    uint32_t kuh[8], kul[8], va0[4], va1[4], vb0[4], vb1[4];

    // ---- stage Q once ----
    {
        const int r = tid >> 1, dseg = (tid & 1) * 32;
        const int wb = r >> 4, gg = r & 7, rh = (r >> 3) & 1;
        const uint32_t* qhw = (const uint32_t*)(QHg + (hb + q0 + r) * DHD) + dseg/2;
        const uint32_t* qlw = (const uint32_t*)(QLg + (hb + q0 + r) * DHD) + dseg/2;
        uint32_t uh[16], ul[16];
        #pragma unroll
        for (int c = 0; c < 4; c++) {
            *(uint4*)&uh[c*4] = *(const uint4*)&qhw[c*4];
            *(uint4*)&ul[c*4] = *(const uint4*)&qlw[c*4];
        }
        #pragma unroll
        for (int c4 = 0; c4 < 8; c4++) {
            const int d0 = dseg + c4*4;
            const int kb = d0 >> 4, cc = d0 & 15;
            const int reg = rh + 2*(cc >> 3), ln = gg*4 + ((cc & 7) >> 1);
            QF[QFI(0,kb,wb,ln,  reg)] = uh[c4*2];
            QF[QFI(0,kb,wb,ln+1,reg)] = uh[c4*2+1];
            QF[QFI(1,kb,wb,ln,  reg)] = ul[c4*2];
            QF[QFI(1,kb,wb,ln+1,reg)] = ul[c4*2+1];
        }
    }
    // ---- stage KV tile 0 directly ----
    {
        *(uint4*)&kuh[0] = *(const uint4*)&khw[0];  *(uint4*)&kuh[4] = *(const uint4*)&khw[4];
        *(uint4*)&kul[0] = *(const uint4*)&klw[0];  *(uint4*)&kul[4] = *(const uint4*)&klw[4];
        *(uint4*)va0 = *(const uint4*)v0h;  *(uint4*)va1 = *(const uint4*)v1h;
        *(uint4*)vb0 = *(const uint4*)v0l;  *(uint4*)vb1 = *(const uint4*)v1l;
        #pragma unroll
        for (int c4 = 0; c4 < 4; c4++) {
            const int cc = c4*4, reg = cc >> 3, t0 = (cc & 7) >> 1;
            KF[KFI(0,kbK,gK*4+t0,  ntK*2+reg)] = kuh[c4*2];
            KF[KFI(0,kbK,gK*4+t0+1,ntK*2+reg)] = kuh[c4*2+1];
            KF[KFI(1,kbK,gK*4+t0,  ntK*2+reg)] = kul[c4*2];
            KF[KFI(1,kbK,gK*4+t0+1,ntK*2+reg)] = kul[c4*2+1];
        }
        #pragma unroll
        for (int j = 0; j < 8; j++) {
            const uint32_t sel = (j & 1) ? 0x7632u : 0x5410u;
            VF[KFI(0,kbV, j*4+tV, ntV*2+regV)] = __byte_perm(va0[j>>1], va1[j>>1], sel);
            VF[KFI(1,kbV, j*4+tV, ntV*2+regV)] = __byte_perm(vb0[j>>1], vb1[j>>1], sel);
        }
    }
    __syncthreads();

    float O[8][4] = {};
    float mx0 = -1e30f, mx1 = -1e30f, l0s = 0.f, l1s = 0.f;

    for (int kt = 0; kt < 32; kt++) {
        const bool more = (kt + 1 < 32);
        if (more) {   // prefetch next tile into regs (LDG latency hides under compute)
            const size_t off = (size_t)(kt+1) * krow;
            *(uint4*)&kuh[0] = *(const uint4*)&khw[off];  *(uint4*)&kuh[4] = *(const uint4*)&khw[off+4];
            *(uint4*)&kul[0] = *(const uint4*)&klw[off];  *(uint4*)&kul[4] = *(const uint4*)&klw[off+4];
            *(uint4*)va0 = *(const uint4*)&v0h[off];  *(uint4*)va1 = *(const uint4*)&v1h[off];
            *(uint4*)vb0 = *(const uint4*)&v0l[off];  *(uint4*)vb1 = *(const uint4*)&v1l[off];
        }

        // ---- S = (Q/8) @ K^T ----
        float S[8][4] = {};
        #pragma unroll
        for (int kb = 0; kb < 4; kb++) {
            uint32_t QH[4], QL[4], kh[16], kl[16];
            *(uint4*)QH = *(const uint4*)&QF[QFI(0,kb,warp,lane,0)];
            *(uint4*)QL = *(const uint4*)&QF[QFI(1,kb,warp,lane,0)];
            #pragma unroll
            for (int q = 0; q < 4; q++) {
                *(uint4*)&kh[q*4] = *(const uint4*)&KF[KFI(0,kb,lane,q*4)];
                *(uint4*)&kl[q*4] = *(const uint4*)&KF[KFI(1,kb,lane,q*4)];
            }
            #pragma unroll
            for (int nt = 0; nt < 8; nt++) {
                mma16(S[nt], QH, kh[nt*2], kh[nt*2+1]);
                mma16(S[nt], QH, kl[nt*2], kl[nt*2+1]);
                mma16(S[nt], QL, kh[nt*2], kh[nt*2+1]);
            }
        }

        // ---- online softmax ----
        float mt0 = -1e30f, mt1 = -1e30f;
        #pragma unroll
        for (int nt = 0; nt < 8; nt++) {
            mt0 = fmaxf(mt0, fmaxf(S[nt][0], S[nt][1]));
            mt1 = fmaxf(mt1, fmaxf(S[nt][2], S[nt][3]));
        }
        #pragma unroll
        for (int off = 2; off >= 1; off >>= 1) {
            mt0 = fmaxf(mt0, __shfl_xor_sync(0xffffffffu, mt0, off));
            mt1 = fmaxf(mt1, __shfl_xor_sync(0xffffffffu, mt1, off));
        }
        const float mn0 = fmaxf(mx0, mt0), mn1 = fmaxf(mx1, mt1);
        const float c0 = __expf(mx0 - mn0), c1 = __expf(mx1 - mn1);
        float ls0 = 0.f, ls1 = 0.f;
        #pragma unroll
        for (int nt = 0; nt < 8; nt++) {
            S[nt][0] = __expf(S[nt][0] - mn0); ls0 += S[nt][0];
            S[nt][1] = __expf(S[nt][1] - mn0); ls0 += S[nt][1];
            S[nt][2] = __expf(S[nt][2] - mn1); ls1 += S[nt][2];
            S[nt][3] = __expf(S[nt][3] - mn1); ls1 += S[nt][3];
        }
        #pragma unroll
        for (int off = 2; off >= 1; off >>= 1) {
            ls0 += __shfl_xor_sync(0xffffffffu, ls0, off);
            ls1 += __shfl_xor_sync(0xffffffffu, ls1, off);
        }
        l0s = l0s * c0 + ls0;  l1s = l1s * c1 + ls1;
        mx0 = mn0;             mx1 = mn1;
        #pragma unroll
        for (int nt = 0; nt < 8; nt++) {
            O[nt][0] *= c0; O[nt][1] *= c0;
            O[nt][2] *= c1; O[nt][3] *= c1;
        }

        // ---- O += P @ V ----
        #pragma unroll
        for (int kb = 0; kb < 4; kb++) {
            uint32_t ph[4], pl[4], vh[16], vl[16];
            split_pair(S[2*kb  ][0], S[2*kb  ][1], ph[0], pl[0]);
            split_pair(S[2*kb  ][2], S[2*kb  ][3], ph[1], pl[1]);
            split_pair(S[2*kb+1][0], S[2*kb+1][1], ph[2], pl[2]);
            split_pair(S[2*kb+1][2], S[2*kb+1][3], ph[3], pl[3]);
            #pragma unroll
            for (int q = 0; q < 4; q++) {
                *(uint4*)&vh[q*4] = *(const uint4*)&VF[KFI(0,kb,lane,q*4)];
                *(uint4*)&vl[q*4] = *(const uint4*)&VF[KFI(1,kb,lane,q*4)];
            }
            #pragma unroll
            for (int nt = 0; nt < 8; nt++) {
                mma16(O[nt], ph, vh[nt*2], vh[nt*2+1]);
                mma16(O[nt], ph, vl[nt*2], vl[nt*2+1]);
                mma16(O[nt], pl, vh[nt*2], vh[nt*2+1]);
            }
        }
        __syncthreads();   // all reads of KF/VF done
        if (more) {        // quick STS of prefetched regs
            #pragma unroll
            for (int c4 = 0; c4 < 4; c4++) {
                const int cc = c4*4, reg = cc >> 3, t0 = (cc & 7) >> 1;
                KF[KFI(0,kbK,gK*4+t0,  ntK*2+reg)] = kuh[c4*2];
                KF[KFI(0,kbK,gK*4+t0+1,ntK*2+reg)] = kuh[c4*2+1];
                KF[KFI(1,kbK,gK*4+t0,  ntK*2+reg)] = kul[c4*2];
                KF[KFI(1,kbK,gK*4+t0+1,ntK*2+reg)] = kul[c4*2+1];
            }
            #pragma unroll
            for (int j = 0; j < 8; j++) {
                const uint32_t sel = (j & 1) ? 0x7632u : 0x5410u;
                VF[KFI(0,kbV, j*4+tV, ntV*2+regV)] = __byte_perm(va0[j>>1], va1[j>>1], sel);
                VF[KFI(1,kbV, j*4+tV, ntV*2+regV)] = __byte_perm(vb0[j>>1], vb1[j>>1], sel);
            }
        }
        __syncthreads();
    }

    // ---- epilogue: normalize, split, write att planes into XH/XL ----
    const float i0 = 1.f / l0s, i1 = 1.f / l1s;
    #pragma unroll
    for (int nt = 0; nt < 8; nt++) {
        const int n = nt*8 + 2*t4;
        const int sa = q0 + warp*16 + g, sb = sa + 8;
        const size_t ia = ((size_t)blockIdx.z * SS + sa) * DD + blockIdx.y * DHD + n;
        const size_t ib = ((size_t)blockIdx.z * SS + sb) * DD + blockIdx.y * DHD + n;
        uint32_t hi, lo;
        split_pair(O[nt][0]*i0, O[nt][1]*i0, hi, lo);
        *(uint32_t*)&XH[ia] = hi; *(uint32_t*)&XL[ia] = lo;
        split_pair(O[nt][2]*i1, O[nt][3]*i1, hi, lo);
        *(uint32_t*)&XH[ib] = hi; *(uint32_t*)&XL[ib] = lo;
    }
}

// ---------------------------------------------------------------------------
// Kernel 3: output projection. A = att planes (pure copy), B = Wo split.
// Double-buffered, one sync/iter. grid (32, 16), dyn smem 53248 B.
// ---------------------------------------------------------------------------
#define OAF(buf) ((buf)*4096)
#define OBF(buf) (8192 + (buf)*2560)
#define OUT_SMEM (13312*4)   // 53248

__global__ __launch_bounds__(256) void out_kernel(
    const float* __restrict__ Wo, const float* __restrict__ bo, float* __restrict__ out)
{
    extern __shared__ uint32_t sm[];
    const int tid  = threadIdx.x;
    const int lane = tid & 31, warp = tid >> 5;
    const int m0 = blockIdx.x * 128;
    const int n0 = blockIdx.y * 64;

    float acc[8][4] = {};

    const int ar = tid >> 1, akb = tid & 1;
    const int awb = ar >> 4, ag = ar & 7, arh = (ar >> 3) & 1;
    const int kp = tid >> 4, n4 = (tid & 15) * 4;
    const int kbB = kp >> 3, regB = (kp >> 2) & 1, tB = kp & 3;

    const uint32_t* xh = (const uint32_t*)(XH + (size_t)(m0 + ar) * DD) + akb*8;
    const uint32_t* xl = (const uint32_t*)(XL + (size_t)(m0 + ar) * DD) + akb*8;

    uint4 pah[2], pal[2];
    float4 pb0, pb1;

    pah[0] = *(const uint4*)&xh[0];  pah[1] = *(const uint4*)&xh[4];
    pal[0] = *(const uint4*)&xl[0];  pal[1] = *(const uint4*)&xl[4];
    pb0 = *(const float4*)&Wo[(size_t)(2*kp  ) * DD + n0 + n4];
    pb1 = *(const float4*)&Wo[(size_t)(2*kp+1) * DD + n0 + n4];
    storeA(sm, OAF(0), pah, pal, akb, awb, ag, arh);
    storeB(sm, OBF(0), pb0, pb1, n4, kbB, regB, tB);
    pah[0] = *(const uint4*)&xh[16];  pah[1] = *(const uint4*)&xh[20];
    pal[0] = *(const uint4*)&xl[16];  pal[1] = *(const uint4*)&xl[20];
    pb0 = *(const float4*)&Wo[(size_t)(32 + 2*kp  ) * DD + n0 + n4];
    pb1 = *(const float4*)&Wo[(size_t)(32 + 2*kp+1) * DD + n0 + n4];
    __syncthreads();

    for (int it = 0; it < 32; it++) {
        const int buf = it & 1;
        if (it + 1 < 32) {
            storeA(sm, OAF(buf^1), pah, pal, akb, awb, ag, arh);
            storeB(sm, OBF(buf^1), pb0, pb1, n4, kbB, regB, tB);
        }
        if (it + 2 < 32) {
            const int w = (it+2)*16;
            pah[0] = *(const uint4*)&xh[w];  pah[1] = *(const uint4*)&xh[w+4];
            pal[0] = *(const uint4*)&xl[w];  pal[1] = *(const uint4*)&xl[w+4];
            const size_t kr = (size_t)(it+2)*32 + 2*kp;
            pb0 = *(const float4*)&Wo[kr*DD + n0 + n4];
            pb1 = *(const float4*)&Wo[(kr+1)*DD + n0 + n4];
        }
        #pragma unroll
        for (int kb = 0; kb < 2; kb++) {
            uint32_t AH[4], AL[4], bh[16], bl[16];
            *(uint4*)AH = *(const uint4*)&sm[OAF(buf) + AFI(0,kb,warp,lane,0)];
            *(uint4*)AL = *(const uint4*)&sm[OAF(buf) + AFI(1,kb,warp,lane,0)];
            #pragma unroll
            for (int q = 0; q < 4; q++) {
                *(uint4*)&bh[q*4] = *(const uint4*)&sm[OBF(buf) + BFI(0,kb,lane,q*4)];
                *(uint4*)&bl[q*4] = *(const uint4*)&sm[OBF(buf) + BFI(1,kb,lane,q*4)];
            }
            #pragma unroll
            for (int nt = 0; nt < 8; nt++) {
                mma16(acc[nt], AH, bh[nt*2], bh[nt*2+1]);
                mma16(acc[nt], AH, bl[nt*2], bl[nt*2+1]);
                mma16(acc[nt], AL, bh[nt*2], bh[nt*2+1]);
            }
        }
        __syncthreads();
    }

    const int g = lane >> 2, t4 = lane & 3;
    #pragma unroll
    for (int nt = 0; nt < 8; nt++) {
        const int n = n0 + nt*8 + 2*t4;
        const float b0 = bo[n], b1 = bo[n+1];
        const int m_a = m0 + warp*16 + g, m_b = m_a + 8;
        *(float2*)&out[(size_t)m_a * DD + n] = make_float2(acc[nt][0] + b0, acc[nt][1] + b1);
        *(float2*)&out[(size_t)m_b * DD + n] = make_float2(acc[nt][2] + b0, acc[nt][3] + b1);
    }
}

// ---------------------------------------------------------------------------
extern "C" void kernel_launch(void* const* d_in, const int* in_sizes, int n_in,
                              void* d_out, int out_size)
{
    (void)in_sizes; (void)n_in; (void)out_size;
    const float* x  = (const float*)d_in[0];
    const float* Wq = (const float*)d_in[1];
    const float* Wk = (const float*)d_in[2];
    const float* Wv = (const float*)d_in[3];
    const float* bq = (const float*)d_in[4];
    const float* bk = (const float*)d_in[5];
    const float* bv = (const float*)d_in[6];
    const float* Wo = (const float*)d_in[7];
    const float* bo = (const float*)d_in[8];
    float* out = (float*)d_out;

    (void)cudaFuncSetAttribute(qkv_kernel,  cudaFuncAttributeMaxDynamicSharedMemorySize, QKV_SMEM);
    (void)cudaFuncSetAttribute(attn_kernel, cudaFuncAttributeMaxDynamicSharedMemorySize, ATT_SMEM_BYTES);
    (void)cudaFuncSetAttribute(out_kernel,  cudaFuncAttributeMaxDynamicSharedMemorySize, OUT_SMEM);

    splitx_kernel<<<(MM*DD)/1024, 256>>>(x);
    qkv_kernel<<<dim3(MM/128, 24), 256, QKV_SMEM>>>(Wq, Wk, Wv, bq, bk, bv);
    attn_kernel<<<dim3(SS/128, HH, BB), 256, ATT_SMEM_BYTES>>>();
    out_kernel<<<dim3(MM/128, DD/64), 256, OUT_SMEM>>>(Wo, bo, out);
}

// round 11
// speedup vs baseline: 2.0277x; 1.0659x over previous
#include <cuda_runtime.h>
#include <cuda_bf16.h>
#include <stdint.h>

#define BB 2
#define SS 2048
#define DD 1024
#define HH 16
#define DHD 64
#define MM (BB*SS)      // 4096
#define NHEAD (BB*HH)   // 32

typedef __nv_bfloat16 bf16;

// ---------------------------------------------------------------------------
// Globals: 8 bf16 planes x 8MB = 64MB (proven-safe set, unchanged from R9).
// XH/XL hold split(x) for qkv, then attn overwrites them with split(att).
// ---------------------------------------------------------------------------
#define DEVARR __device__ __align__(16)
DEVARR bf16 XH [(size_t)MM*DD];        DEVARR bf16 XL [(size_t)MM*DD];
DEVARR bf16 QHg[(size_t)NHEAD*SS*DHD]; DEVARR bf16 QLg[(size_t)NHEAD*SS*DHD];
DEVARR bf16 KHg[(size_t)NHEAD*SS*DHD]; DEVARR bf16 KLg[(size_t)NHEAD*SS*DHD];
DEVARR bf16 VHg[(size_t)NHEAD*SS*DHD]; DEVARR bf16 VLg[(size_t)NHEAD*SS*DHD];

// ---------------------------------------------------------------------------
__device__ __forceinline__ void split_pair(float x0, float x1, uint32_t& hi, uint32_t& lo) {
    __nv_bfloat16 h0 = __float2bfloat16_rn(x0);
    __nv_bfloat16 h1 = __float2bfloat16_rn(x1);
    __nv_bfloat16 l0 = __float2bfloat16_rn(x0 - __bfloat162float(h0));
    __nv_bfloat16 l1 = __float2bfloat16_rn(x1 - __bfloat162float(h1));
    hi = ((uint32_t)__bfloat16_as_ushort(h1) << 16) | (uint32_t)__bfloat16_as_ushort(h0);
    lo = ((uint32_t)__bfloat16_as_ushort(l1) << 16) | (uint32_t)__bfloat16_as_ushort(l0);
}
__device__ __forceinline__ void mma16(float* d, const uint32_t* a, uint32_t b0, uint32_t b1) {
    asm volatile("mma.sync.aligned.m16n8k16.row.col.f32.bf16.bf16.f32 "
        "{%0,%1,%2,%3}, {%4,%5,%6,%7}, {%8,%9}, {%0,%1,%2,%3};"
        : "+f"(d[0]), "+f"(d[1]), "+f"(d[2]), "+f"(d[3])
        : "r"(a[0]), "r"(a[1]), "r"(a[2]), "r"(a[3]), "r"(b0), "r"(b1));
}

// A-frag layout (R5/8/9 proven): [split][kb][warpblock][lane][reg]  (4096 words)
#define AFI(s,kb,wb,l,r) (((((s)*2+(kb))*8+(wb))*32+(l))*4+(r))
// B-frag layout for n128: [split][kb][lane][idx 0..31], stride 36 (4608 words)
#define BFI2(s,kb,l,i)   ((((s)*2+(kb))*32+(l))*36+(i))

// ---------------------------------------------------------------------------
// prep: split x into hi/lo planes (one time)
// ---------------------------------------------------------------------------
__global__ __launch_bounds__(256) void splitx_kernel(const float* __restrict__ src) {
    const size_t i = ((size_t)blockIdx.x * 256 + threadIdx.x) * 4;
    const float4 v = *(const float4*)&src[i];
    uint32_t h0, l0, h1, l1;
    split_pair(v.x, v.y, h0, l0);
    split_pair(v.z, v.w, h1, l1);
    *(uint2*)&XH[i] = make_uint2(h0, h1);
    *(uint2*)&XL[i] = make_uint2(l0, l1);
}

// staging helpers
__device__ __forceinline__ void storeA_frag(uint32_t* smA,
    const uint4* pah, const uint4* pal, int akb, int awb, int ag, int arh)
{
    uint32_t uh[8], ul[8];
    *(uint4*)&uh[0] = pah[0];  *(uint4*)&uh[4] = pah[1];
    *(uint4*)&ul[0] = pal[0];  *(uint4*)&ul[4] = pal[1];
    #pragma unroll
    for (int c4 = 0; c4 < 4; c4++) {
        const int cc = c4*4, chalf = cc >> 3, t0 = (cc & 7) >> 1;
        const int reg = arh + 2*chalf, ln = ag*4 + t0;
        smA[AFI(0,akb,awb,ln,  reg)] = uh[2*c4];
        smA[AFI(0,akb,awb,ln+1,reg)] = uh[2*c4+1];
        smA[AFI(1,akb,awb,ln,  reg)] = ul[2*c4];
        smA[AFI(1,akb,awb,ln+1,reg)] = ul[2*c4+1];
    }
}
__device__ __forceinline__ void storeB_frag(uint32_t* smB,
    float4 r0a, float4 r0b, float4 r1a, float4 r1b,
    int ntB, int kbB, int regB, int tB)
{
    const float w0[8] = {r0a.x,r0a.y,r0a.z,r0a.w, r0b.x,r0b.y,r0b.z,r0b.w};
    const float w1[8] = {r1a.x,r1a.y,r1a.z,r1a.w, r1b.x,r1b.y,r1b.z,r1b.w};
    #pragma unroll
    for (int j = 0; j < 8; j++) {
        uint32_t hh, ll;
        split_pair(w0[j], w1[j], hh, ll);
        smB[BFI2(0,kbB, j*4+tB, ntB*2+regB)] = hh;
        smB[BFI2(1,kbB, j*4+tB, ntB*2+regB)] = ll;
    }
}

// ---------------------------------------------------------------------------
// GEMM mainloop shape (attn clone): per iter
//   [LDG next chunk -> regs]  [96 MMAs on smem]  sync  [STS next]  sync
// C[m128 x n128] = Asplit[m128 x 1024] @ B[1024 x n128], BK=32.
// 8 warps, warp = m16 x n128. smem static 34816 B.
// ---------------------------------------------------------------------------
#define GEMM_BODY(A_H, A_L, BROW_STRIDE, WSRC)                                      \
    __shared__ uint32_t smA[4096];                                                  \
    __shared__ uint32_t smB[4608];                                                  \
    const int tid  = threadIdx.x;                                                   \
    const int lane = tid & 31, warp = tid >> 5;                                     \
    const int ar = tid >> 1, akb = tid & 1;                                         \
    const int awb = ar >> 4, ag = ar & 7, arh = (ar >> 3) & 1;                      \
    const int kp = tid >> 4, ntB = tid & 15;                                        \
    const int kbB = kp >> 3, regB = (kp >> 2) & 1, tB = kp & 3;                     \
    const uint32_t* xh = (const uint32_t*)(A_H) + akb*8;                            \
    const uint32_t* xl = (const uint32_t*)(A_L) + akb*8;                            \
    float acc[16][4] = {};                                                          \
    uint4 pah[2], pal[2];                                                           \
    float4 r0a, r0b, r1a, r1b;                                                      \
    /* prime chunk 0 */                                                             \
    pah[0] = *(const uint4*)&xh[0];  pah[1] = *(const uint4*)&xh[4];                \
    pal[0] = *(const uint4*)&xl[0];  pal[1] = *(const uint4*)&xl[4];                \
    {   const float* wr = WSRC + (size_t)(2*kp) * (BROW_STRIDE);                    \
        r0a = *(const float4*)&wr[0];  r0b = *(const float4*)&wr[4];                \
        r1a = *(const float4*)&wr[BROW_STRIDE];                                     \
        r1b = *(const float4*)&wr[BROW_STRIDE+4]; }                                 \
    storeA_frag(smA, pah, pal, akb, awb, ag, arh);                                  \
    storeB_frag(smB, r0a, r0b, r1a, r1b, ntB, kbB, regB, tB);                       \
    __syncthreads();                                                                \
    for (int it = 0; it < 32; it++) {                                               \
        const bool more = (it + 1 < 32);                                            \
        if (more) {                                                                 \
            const int w = (it+1)*16;                                                \
            pah[0] = *(const uint4*)&xh[w];  pah[1] = *(const uint4*)&xh[w+4];      \
            pal[0] = *(const uint4*)&xl[w];  pal[1] = *(const uint4*)&xl[w+4];      \
            const float* wr = WSRC + (size_t)((it+1)*32 + 2*kp) * (BROW_STRIDE);    \
            r0a = *(const float4*)&wr[0];  r0b = *(const float4*)&wr[4];            \
            r1a = *(const float4*)&wr[BROW_STRIDE];                                 \
            r1b = *(const float4*)&wr[BROW_STRIDE+4];                               \
        }                                                                           \
        _Pragma("unroll")                                                           \
        for (int kb = 0; kb < 2; kb++) {                                            \
            uint32_t AH[4], AL[4];                                                  \
            *(uint4*)AH = *(const uint4*)&smA[AFI(0,kb,warp,lane,0)];               \
            *(uint4*)AL = *(const uint4*)&smA[AFI(1,kb,warp,lane,0)];               \
            _Pragma("unroll")                                                       \
            for (int q = 0; q < 8; q++) {                                           \
                const uint4 h4 = *(const uint4*)&smB[BFI2(0,kb,lane,4*q)];          \
                const uint4 l4 = *(const uint4*)&smB[BFI2(1,kb,lane,4*q)];          \
                mma16(acc[2*q],   AH, h4.x, h4.y);                                  \
                mma16(acc[2*q],   AH, l4.x, l4.y);                                  \
                mma16(acc[2*q],   AL, h4.x, h4.y);                                  \
                mma16(acc[2*q+1], AH, h4.z, h4.w);                                  \
                mma16(acc[2*q+1], AH, l4.z, l4.w);                                  \
                mma16(acc[2*q+1], AL, h4.z, h4.w);                                  \
            }                                                                       \
        }                                                                           \
        __syncthreads();                                                            \
        if (more) {                                                                 \
            storeA_frag(smA, pah, pal, akb, awb, ag, arh);                          \
            storeB_frag(smB, r0a, r0b, r1a, r1b, ntB, kbB, regB, tB);               \
        }                                                                           \
        __syncthreads();                                                            \
    }

// ---------------------------------------------------------------------------
// Kernel 1: fused QKV projection. 2 heads/block (n128). grid (32, 24), 256 thr.
// ---------------------------------------------------------------------------
__global__ __launch_bounds__(256) void qkv_kernel(
    const float* __restrict__ Wq, const float* __restrict__ Wk, const float* __restrict__ Wv,
    const float* __restrict__ bq, const float* __restrict__ bk, const float* __restrict__ bv)
{
    const int m0 = blockIdx.x * 128;
    const int which = blockIdx.y >> 3, hp = blockIdx.y & 7;
    const int h0 = 2*hp, h1 = 2*hp + 1;
    const float* Wb = (which == 0) ? Wq : (which == 1) ? Wk : Wv;
    // thread's B column base: head by ntB half, col (ntB&7)*8 within head
    const int ntB_pre = threadIdx.x & 15;
    const float* wsrc = Wb + (size_t)((ntB_pre < 8) ? h0 : h1) * DD * DHD + (ntB_pre & 7) * 8;

    GEMM_BODY(XH + (size_t)(m0 + (threadIdx.x>>1)) * DD,
              XL + (size_t)(m0 + (threadIdx.x>>1)) * DD,
              DHD, wsrc)

    // epilogue: bias, scale(q), split, store planes (R9 verbatim)
    const float* biasb = (which == 0) ? bq : (which == 1) ? bk : bv;
    bf16* oh = (which == 0) ? QHg : (which == 1) ? KHg : VHg;
    bf16* ol = (which == 0) ? QLg : (which == 1) ? KLg : VLg;
    const float sc = (which == 0) ? 0.125f : 1.0f;

    const int g = lane >> 2, t4 = lane & 3;
    #pragma unroll
    for (int idx = 0; idx < 16; idx++) {
        const int head = (idx < 8) ? h0 : h1;
        const int n64 = (idx & 7)*8 + 2*t4;
        const float b0 = biasb[head*DHD + n64], b1 = biasb[head*DHD + n64 + 1];
        uint32_t hi, lo;
        int m = m0 + warp*16 + g;
        size_t ridx = (((size_t)(m >> 11) * HH + head) * SS + (m & (SS-1))) * DHD + n64;
        split_pair((acc[idx][0] + b0) * sc, (acc[idx][1] + b1) * sc, hi, lo);
        *(uint32_t*)&oh[ridx] = hi; *(uint32_t*)&ol[ridx] = lo;
        m += 8;
        ridx = (((size_t)(m >> 11) * HH + head) * SS + (m & (SS-1))) * DHD + n64;
        split_pair((acc[idx][2] + b0) * sc, (acc[idx][3] + b1) * sc, hi, lo);
        *(uint32_t*)&oh[ridx] = hi; *(uint32_t*)&ol[ridx] = lo;
    }
}

// ---------------------------------------------------------------------------
// Kernel 3: output projection. n128/block. grid (32, 8), 256 thr.
// ---------------------------------------------------------------------------
__global__ __launch_bounds__(256) void out_kernel(
    const float* __restrict__ Wo, const float* __restrict__ bo, float* __restrict__ out)
{
    const int m0 = blockIdx.x * 128;
    const int n0 = blockIdx.y * 128;
    const int ntB_pre = threadIdx.x & 15;
    const float* wsrc = Wo + n0 + ntB_pre * 8;

    GEMM_BODY(XH + (size_t)(m0 + (threadIdx.x>>1)) * DD,
              XL + (size_t)(m0 + (threadIdx.x>>1)) * DD,
              DD, wsrc)

    const int g = lane >> 2, t4 = lane & 3;
    #pragma unroll
    for (int nt = 0; nt < 16; nt++) {
        const int n = n0 + nt*8 + 2*t4;
        const float b0 = bo[n], b1 = bo[n+1];
        const int m_a = m0 + warp*16 + g, m_b = m_a + 8;
        *(float2*)&out[(size_t)m_a * DD + n] = make_float2(acc[nt][0] + b0, acc[nt][1] + b1);
        *(float2*)&out[(size_t)m_b * DD + n] = make_float2(acc[nt][2] + b0, acc[nt][3] + b1);
    }
}

// ---------------------------------------------------------------------------
// Kernel 2: flash attention (round-9 VERBATIM — measured 51% tensor).
// grid (16, 16, 2), 256 thr, dyn smem 73728 B.
// ---------------------------------------------------------------------------
#define QFI(s,kb,wb,l,r) (((((s)*4+(kb))*8+(wb))*32+(l))*4+(r))   // 8192 words
#define KFI(s,kb,l,i)    ((((s)*4+(kb))*32+(l))*20+(i))           // 5120 words
#define ATT_SMEM_BYTES ((8192 + 5120 + 5120) * 4)

__global__ __launch_bounds__(256) void attn_kernel()
{
    extern __shared__ uint32_t sm[];
    uint32_t* QF = sm;
    uint32_t* KF = sm + 8192;
    uint32_t* VF = sm + 13312;

    const int tid  = threadIdx.x;
    const int lane = tid & 31, warp = tid >> 5;
    const int g = lane >> 2, t4 = lane & 3;
    const int q0 = blockIdx.x * 128;
    const int head = blockIdx.z * HH + blockIdx.y;
    const size_t hb = (size_t)head * SS;

    const int key = tid >> 2, kbK = tid & 3;
    const int gK = key & 7, ntK = key >> 3;
    const int kpV = tid >> 3, d8 = (tid & 7) * 8;
    const int kbV = kpV >> 3, regV = (kpV >> 2) & 1, tV = kpV & 3, ntV = tid & 7;

    const uint32_t* khw = (const uint32_t*)(KHg + (hb + key) * DHD) + kbK*8;
    const uint32_t* klw = (const uint32_t*)(KLg + (hb + key) * DHD) + kbK*8;
    const uint32_t* v0h = (const uint32_t*)(VHg + (hb + 2*kpV    ) * DHD) + d8/2;
    const uint32_t* v1h = (const uint32_t*)(VHg + (hb + 2*kpV + 1) * DHD) + d8/2;
    const uint32_t* v0l = (const uint32_t*)(VLg + (hb + 2*kpV    ) * DHD) + d8/2;
    const uint32_t* v1l = (const uint32_t*)(VLg + (hb + 2*kpV + 1) * DHD) + d8/2;
    const size_t krow = (size_t)64 * DHD / 2;

    uint32_t kuh[8], kul[8], va0[4], va1[4], vb0[4], vb1[4];

    {   // stage Q once
        const int r = tid >> 1, dseg = (tid & 1) * 32;
        const int wb = r >> 4, gg = r & 7, rh = (r >> 3) & 1;
        const uint32_t* qhw = (const uint32_t*)(QHg + (hb + q0 + r) * DHD) + dseg/2;
        const uint32_t* qlw = (const uint32_t*)(QLg + (hb + q0 + r) * DHD) + dseg/2;
        uint32_t uh[16], ul[16];
        #pragma unroll
        for (int c = 0; c < 4; c++) {
            *(uint4*)&uh[c*4] = *(const uint4*)&qhw[c*4];
            *(uint4*)&ul[c*4] = *(const uint4*)&qlw[c*4];
        }
        #pragma unroll
        for (int c4 = 0; c4 < 8; c4++) {
            const int d0 = dseg + c4*4;
            const int kb = d0 >> 4, cc = d0 & 15;
            const int reg = rh + 2*(cc >> 3), ln = gg*4 + ((cc & 7) >> 1);
            QF[QFI(0,kb,wb,ln,  reg)] = uh[c4*2];
            QF[QFI(0,kb,wb,ln+1,reg)] = uh[c4*2+1];
            QF[QFI(1,kb,wb,ln,  reg)] = ul[c4*2];
            QF[QFI(1,kb,wb,ln+1,reg)] = ul[c4*2+1];
        }
    }
    {   // stage KV tile 0
        *(uint4*)&kuh[0] = *(const uint4*)&khw[0];  *(uint4*)&kuh[4] = *(const uint4*)&khw[4];
        *(uint4*)&kul[0] = *(const uint4*)&klw[0];  *(uint4*)&kul[4] = *(const uint4*)&klw[4];
        *(uint4*)va0 = *(const uint4*)v0h;  *(uint4*)va1 = *(const uint4*)v1h;
        *(uint4*)vb0 = *(const uint4*)v0l;  *(uint4*)vb1 = *(const uint4*)v1l;
        #pragma unroll
        for (int c4 = 0; c4 < 4; c4++) {
            const int cc = c4*4, reg = cc >> 3, t0 = (cc & 7) >> 1;
            KF[KFI(0,kbK,gK*4+t0,  ntK*2+reg)] = kuh[c4*2];
            KF[KFI(0,kbK,gK*4+t0+1,ntK*2+reg)] = kuh[c4*2+1];
            KF[KFI(1,kbK,gK*4+t0,  ntK*2+reg)] = kul[c4*2];
            KF[KFI(1,kbK,gK*4+t0+1,ntK*2+reg)] = kul[c4*2+1];
        }
        #pragma unroll
        for (int j = 0; j < 8; j++) {
            const uint32_t sel = (j & 1) ? 0x7632u : 0x5410u;
            VF[KFI(0,kbV, j*4+tV, ntV*2+regV)] = __byte_perm(va0[j>>1], va1[j>>1], sel);
            VF[KFI(1,kbV, j*4+tV, ntV*2+regV)] = __byte_perm(vb0[j>>1], vb1[j>>1], sel);
        }
    }
    __syncthreads();

    float O[8][4] = {};
    float mx0 = -1e30f, mx1 = -1e30f, l0s = 0.f, l1s = 0.f;

    for (int kt = 0; kt < 32; kt++) {
        const bool more = (kt + 1 < 32);
        if (more) {
            const size_t off = (size_t)(kt+1) * krow;
            *(uint4*)&kuh[0] = *(const uint4*)&khw[off];  *(uint4*)&kuh[4] = *(const uint4*)&khw[off+4];
            *(uint4*)&kul[0] = *(const uint4*)&klw[off];  *(uint4*)&kul[4] = *(const uint4*)&klw[off+4];
            *(uint4*)va0 = *(const uint4*)&v0h[off];  *(uint4*)va1 = *(const uint4*)&v1h[off];
            *(uint4*)vb0 = *(const uint4*)&v0l[off];  *(uint4*)vb1 = *(const uint4*)&v1l[off];
        }

        float S[8][4] = {};
        #pragma unroll
        for (int kb = 0; kb < 4; kb++) {
            uint32_t QH[4], QL[4], kh[16], kl[16];
            *(uint4*)QH = *(const uint4*)&QF[QFI(0,kb,warp,lane,0)];
            *(uint4*)QL = *(const uint4*)&QF[QFI(1,kb,warp,lane,0)];
            #pragma unroll
            for (int q = 0; q < 4; q++) {
                *(uint4*)&kh[q*4] = *(const uint4*)&KF[KFI(0,kb,lane,q*4)];
                *(uint4*)&kl[q*4] = *(const uint4*)&KF[KFI(1,kb,lane,q*4)];
            }
            #pragma unroll
            for (int nt = 0; nt < 8; nt++) {
                mma16(S[nt], QH, kh[nt*2], kh[nt*2+1]);
                mma16(S[nt], QH, kl[nt*2], kl[nt*2+1]);
                mma16(S[nt], QL, kh[nt*2], kh[nt*2+1]);
            }
        }

        float mt0 = -1e30f, mt1 = -1e30f;
        #pragma unroll
        for (int nt = 0; nt < 8; nt++) {
            mt0 = fmaxf(mt0, fmaxf(S[nt][0], S[nt][1]));
            mt1 = fmaxf(mt1, fmaxf(S[nt][2], S[nt][3]));
        }
        #pragma unroll
        for (int off = 2; off >= 1; off >>= 1) {
            mt0 = fmaxf(mt0, __shfl_xor_sync(0xffffffffu, mt0, off));
            mt1 = fmaxf(mt1, __shfl_xor_sync(0xffffffffu, mt1, off));
        }
        const float mn0 = fmaxf(mx0, mt0), mn1 = fmaxf(mx1, mt1);
        const float c0 = __expf(mx0 - mn0), c1 = __expf(mx1 - mn1);
        float ls0 = 0.f, ls1 = 0.f;
        #pragma unroll
        for (int nt = 0; nt < 8; nt++) {
            S[nt][0] = __expf(S[nt][0] - mn0); ls0 += S[nt][0];
            S[nt][1] = __expf(S[nt][1] - mn0); ls0 += S[nt][1];
            S[nt][2] = __expf(S[nt][2] - mn1); ls1 += S[nt][2];
            S[nt][3] = __expf(S[nt][3] - mn1); ls1 += S[nt][3];
        }
        #pragma unroll
        for (int off = 2; off >= 1; off >>= 1) {
            ls0 += __shfl_xor_sync(0xffffffffu, ls0, off);
            ls1 += __shfl_xor_sync(0xffffffffu, ls1, off);
        }
        l0s = l0s * c0 + ls0;  l1s = l1s * c1 + ls1;
        mx0 = mn0;             mx1 = mn1;
        #pragma unroll
        for (int nt = 0; nt < 8; nt++) {
            O[nt][0] *= c0; O[nt][1] *= c0;
            O[nt][2] *= c1; O[nt][3] *= c1;
        }

        #pragma unroll
        for (int kb = 0; kb < 4; kb++) {
            uint32_t ph[4], pl[4], vh[16], vl[16];
            split_pair(S[2*kb  ][0], S[2*kb  ][1], ph[0], pl[0]);
            split_pair(S[2*kb  ][2], S[2*kb  ][3], ph[1], pl[1]);
            split_pair(S[2*kb+1][0], S[2*kb+1][1], ph[2], pl[2]);
            split_pair(S[2*kb+1][2], S[2*kb+1][3], ph[3], pl[3]);
            #pragma unroll
            for (int q = 0; q < 4; q++) {
                *(uint4*)&vh[q*4] = *(const uint4*)&VF[KFI(0,kb,lane,q*4)];
                *(uint4*)&vl[q*4] = *(const uint4*)&VF[KFI(1,kb,lane,q*4)];
            }
            #pragma unroll
            for (int nt = 0; nt < 8; nt++) {
                mma16(O[nt], ph, vh[nt*2], vh[nt*2+1]);
                mma16(O[nt], ph, vl[nt*2], vl[nt*2+1]);
                mma16(O[nt], pl, vh[nt*2], vh[nt*2+1]);
            }
        }
        __syncthreads();
        if (more) {
            #pragma unroll
            for (int c4 = 0; c4 < 4; c4++) {
                const int cc = c4*4, reg = cc >> 3, t0 = (cc & 7) >> 1;
                KF[KFI(0,kbK,gK*4+t0,  ntK*2+reg)] = kuh[c4*2];
                KF[KFI(0,kbK,gK*4+t0+1,ntK*2+reg)] = kuh[c4*2+1];
                KF[KFI(1,kbK,gK*4+t0,  ntK*2+reg)] = kul[c4*2];
                KF[KFI(1,kbK,gK*4+t0+1,ntK*2+reg)] = kul[c4*2+1];
            }
            #pragma unroll
            for (int j = 0; j < 8; j++) {
                const uint32_t sel = (j & 1) ? 0x7632u : 0x5410u;
                VF[KFI(0,kbV, j*4+tV, ntV*2+regV)] = __byte_perm(va0[j>>1], va1[j>>1], sel);
                VF[KFI(1,kbV, j*4+tV, ntV*2+regV)] = __byte_perm(vb0[j>>1], vb1[j>>1], sel);
            }
        }
        __syncthreads();
    }

    const float i0 = 1.f / l0s, i1 = 1.f / l1s;
    #pragma unroll
    for (int nt = 0; nt < 8; nt++) {
        const int n = nt*8 + 2*t4;
        const int sa = q0 + warp*16 + g, sb = sa + 8;
        const size_t ia = ((size_t)blockIdx.z * SS + sa) * DD + blockIdx.y * DHD + n;
        const size_t ib = ((size_t)blockIdx.z * SS + sb) * DD + blockIdx.y * DHD + n;
        uint32_t hi, lo;
        split_pair(O[nt][0]*i0, O[nt][1]*i0, hi, lo);
        *(uint32_t*)&XH[ia] = hi; *(uint32_t*)&XL[ia] = lo;
        split_pair(O[nt][2]*i1, O[nt][3]*i1, hi, lo);
        *(uint32_t*)&XH[ib] = hi; *(uint32_t*)&XL[ib] = lo;
    }
}

// ---------------------------------------------------------------------------
extern "C" void kernel_launch(void* const* d_in, const int* in_sizes, int n_in,
                              void* d_out, int out_size)
{
    (void)in_sizes; (void)n_in; (void)out_size;
    const float* x  = (const float*)d_in[0];
    const float* Wq = (const float*)d_in[1];
    const float* Wk = (const float*)d_in[2];
    const float* Wv = (const float*)d_in[3];
    const float* bq = (const float*)d_in[4];
    const float* bk = (const float*)d_in[5];
    const float* bv = (const float*)d_in[6];
    const float* Wo = (const float*)d_in[7];
    const float* bo = (const float*)d_in[8];
    float* out = (float*)d_out;

    (void)cudaFuncSetAttribute(attn_kernel, cudaFuncAttributeMaxDynamicSharedMemorySize,
                               ATT_SMEM_BYTES);

    splitx_kernel<<<(MM*DD)/1024, 256>>>(x);
    qkv_kernel<<<dim3(MM/128, 24), 256>>>(Wq, Wk, Wv, bq, bk, bv);
    attn_kernel<<<dim3(SS/128, HH, BB), 256, ATT_SMEM_BYTES>>>();
    out_kernel<<<dim3(MM/128, DD/128), 256>>>(Wo, bo, out);
}